// round 6
// baseline (speedup 1.0000x reference)
#include <cuda_runtime.h>
#include <cuda_fp16.h>
#include <cstdint>
#include <math.h>

#define NT  365
#define NS  256
#define NH  256
#define NG  32
#define NR  16
#define HID 256
#define NTS (NT*NS)          // 93440
#define TOUT (NT-NR+1)       // 350
#define MTILES 730           // 93440/128
#define QSTR 372             // padded time stride for transposed Q
#define TCHUNK 92            // hiddenT t-chunk (4*92=368 >= 365)

// ---------------- scratch (device globals) ----------------------------------
__device__ __half g_hiddenH[NTS*HID]; // fcT layer-1 output (tanh, fp16)
__device__ __half g_PlH[NTS*NH];
__device__ __half g_EvH[NTS*NH];
__device__ __half g_VmH[NTS*NH];
__device__ float g_Qt[NS*NH*QSTR];    // time-contiguous Q
__device__ float g_hidW[NS*HID];
__device__ float g_hidR[NS*HID];
__device__ float g_baseT[NS*HID];
__device__ float g_w[NS*NH*7];
__device__ float g_rfraw[NS*NH*NR];
__device__ float g_kp[NS*NH], g_ks[NS*NH], g_kg[NS*NH], g_gp[NS*NH];
__device__ float g_gL[NS*NH], g_qb[NS*NH], g_ga[NS*NH];
__device__ float g_r[NS*NH*NR];
__device__ float g_PsT[NS*QSTR];      // snowfall, transposed [s][t]
__device__ float g_pfrac[NTS];
__device__ __half g_w2tH[768*HID];    // fcT_w2^T, fp16

__device__ __forceinline__ float sigf(float x){ return 1.0f/(1.0f+expf(-x)); }
__device__ __forceinline__ float tanha(float x){
    float y; asm("tanh.approx.f32 %0, %1;" : "=f"(y) : "f"(x)); return y;
}

__device__ __forceinline__ uint32_t smem_u32(const void* p){
    uint32_t a;
    asm("{ .reg .u64 t; cvta.to.shared.u64 t, %1; cvt.u32.u64 %0, t; }" : "=r"(a) : "l"(p));
    return a;
}
__device__ __forceinline__ void cpa16(uint32_t dst, const void* src){
    asm volatile("cp.async.cg.shared.global [%0], [%1], 16;" :: "r"(dst), "l"(src) : "memory");
}
#define CP_COMMIT() asm volatile("cp.async.commit_group;" ::: "memory")
template<int N> __device__ __forceinline__ void cpwait(){
    asm volatile("cp.async.wait_group %0;" :: "n"(N) : "memory");
}
#define LDSM_X4(r0,r1,r2,r3,addr) \
    asm volatile("ldmatrix.sync.aligned.m8n8.x4.shared.b16 {%0,%1,%2,%3}, [%4];" \
        : "=r"(r0),"=r"(r1),"=r"(r2),"=r"(r3) : "r"(addr))
#define MMA_F16(c0,c1,c2,c3,a0,a1,a2,a3,b0,b1) \
    asm volatile("mma.sync.aligned.m16n8k16.row.col.f32.f16.f16.f32 " \
        "{%0,%1,%2,%3}, {%4,%5,%6,%7}, {%8,%9}, {%0,%1,%2,%3};" \
        : "+f"(c0),"+f"(c1),"+f"(c2),"+f"(c3) \
        : "r"(a0),"r"(a1),"r"(a2),"r"(a3), "r"(b0),"r"(b1))

// ============ setup: prep + transposeB(fp16) + layer1 in one launch =========
__global__ void __launch_bounds__(256) setup_kernel(
        const float* __restrict__ x, const float* __restrict__ xc,
        const float* __restrict__ w2,
        const float* __restrict__ wW1, const float* __restrict__ bW1,
        const float* __restrict__ wR1, const float* __restrict__ bR1,
        const float* __restrict__ wT1, const float* __restrict__ bT1){
    __shared__ float sh[32*33];
    int bid = blockIdx.x, tid = threadIdx.x;
    if (bid < 365){
        int i = bid*256 + tid;
        float P  = x[i*6+0];
        float T1 = x[i*6+2];
        float T2 = x[i*6+3];
        float ratio = (T1+T2)/(T2-T1);
        ratio = fminf(fmaxf(ratio,-1.0f),1.0f);
        float vf = acosf(ratio)/3.1415f;
        if (T1 >= 0.0f) vf = 0.0f;
        if (T2 <= 0.0f) vf = 1.0f;
        int s = i & 255, t = i >> 8;
        g_PsT[s*QSTR + t] = P*vf;
        g_pfrac[i] = P*(1.0f-vf);
    } else if (bid < 365+192){
        int tb = bid - 365;
        int nb = (tb % 24)*32, kb = (tb / 24)*32;
        int tx = tid & 31, ty = tid >> 5;
        #pragma unroll
        for (int r = 0; r < 32; r += 8)
            sh[(ty+r)*33 + tx] = w2[(kb+ty+r)*768 + nb + tx];
        __syncthreads();
        #pragma unroll
        for (int r = 0; r < 32; r += 8)
            g_w2tH[(nb+ty+r)*HID + kb + tx] = __float2half(sh[tx*33 + ty + r]);
    } else {
        int lb = bid - 557;
        int s = lb & 255, mode = lb >> 8, h = tid;
        float* xs = sh;
        if (h < NG) xs[h] = xc[s*NG + h];
        __syncthreads();
        const float* w; const float* b; float* out; bool dotanh;
        if (mode == 0){ w = wW1;      b = bW1; out = g_hidW;  dotanh = true;  }
        else if (mode == 1){ w = wR1; b = bR1; out = g_hidR;  dotanh = true;  }
        else { w = wT1 + 6*HID;       b = bT1; out = g_baseT; dotanh = false; }
        float acc = b[h];
        #pragma unroll
        for (int g = 0; g < NG; g++) acc += xs[g]*w[g*HID + h];
        out[s*HID + h] = dotanh ? tanhf(acc) : acc;
    }
}

// ---------------- fcT layer-1: block per (s, t-chunk), regs-resident weights -
__global__ void __launch_bounds__(128) hiddenT_kernel(const float* __restrict__ x,
                                                      const float* __restrict__ wT1){
    const int s = blockIdx.x;
    const int t0 = blockIdx.y*TCHUNK;
    const int t1 = min(t0 + TCHUNK, NT);
    const int nt = t1 - t0;
    const int hl = threadIdx.x, hh = hl*2;

    float w0[6], w1[6];
    #pragma unroll
    for (int i = 0; i < 6; i++){
        w0[i] = wT1[i*HID + hh];
        w1[i] = wT1[i*HID + hh + 1];
    }
    const float b0 = g_baseT[s*HID + hh];
    const float b1 = g_baseT[s*HID + hh + 1];

    __shared__ float sx[TCHUNK*6];
    for (int u = hl; u < nt*6; u += 128){
        int j = u/6, i = u - j*6;
        sx[u] = x[(size_t)(t0 + j)*(NS*6) + s*6 + i];
    }
    __syncthreads();

    __half* dst = g_hiddenH + ((size_t)(t0*NS + s))*HID + hh;
    #pragma unroll 4
    for (int j = 0; j < nt; j++){
        const float* xv = sx + j*6;
        float a0 = b0, a1 = b1;
        #pragma unroll
        for (int i = 0; i < 6; i++){
            float f = xv[i];
            a0 += f*w0[i];
            a1 += f*w1[i];
        }
        *(half2*)(dst + (size_t)j*(NS*HID)) = __floats2half2_rn(tanha(a0), tanha(a1));
    }
}

// ---------------- combined small SIMT GEMMs (fcW + fcR layer 2) -------------
#define BM 128
#define BN 64
#define BK 32
#define KK 256

__global__ void __launch_bounds__(256) gemmWR_kernel(
        const float* __restrict__ Wb, const float* __restrict__ Wbias,
        const float* __restrict__ Rb, const float* __restrict__ Rbias){
    const float* A; float* C; const float* B; const float* bias; int N; int bn;
    if (blockIdx.x < 28){ A = g_hidW; C = g_w;     B = Wb; bias = Wbias; N = NH*7;  bn = blockIdx.x; }
    else                { A = g_hidR; C = g_rfraw; B = Rb; bias = Rbias; N = NH*NR; bn = blockIdx.x - 28; }

    __shared__ float As[2][BK][BM];
    __shared__ float Bs[2][BK][BN];

    const int tid = threadIdx.x;
    const int tx  = tid & 15;
    const int ty  = tid >> 4;
    const int bm  = blockIdx.y;

    const float* Ag = A + bm*BM*KK;
    const float* Bg = B + bn*BN;

    float acc[8][4];
    #pragma unroll
    for (int i = 0; i < 8; i++)
        #pragma unroll
        for (int j = 0; j < 4; j++) acc[i][j] = 0.0f;

    float4 ra[4], rb[2];
    auto ldg_tile = [&](int k0){
        #pragma unroll
        for (int i = 0; i < 4; i++){
            int f = tid + i*256;
            int row = f >> 3, c4 = f & 7;
            ra[i] = *(const float4*)(Ag + row*KK + k0 + c4*4);
        }
        #pragma unroll
        for (int i = 0; i < 2; i++){
            int f = tid + i*256;
            int row = f >> 4, c4 = f & 15;
            rb[i] = *(const float4*)(Bg + (k0 + row)*N + c4*4);
        }
    };
    auto sts_tile = [&](int buf){
        #pragma unroll
        for (int i = 0; i < 4; i++){
            int f = tid + i*256;
            int row = f >> 3, c4 = f & 7;
            As[buf][c4*4+0][row] = ra[i].x;
            As[buf][c4*4+1][row] = ra[i].y;
            As[buf][c4*4+2][row] = ra[i].z;
            As[buf][c4*4+3][row] = ra[i].w;
        }
        #pragma unroll
        for (int i = 0; i < 2; i++){
            int f = tid + i*256;
            int row = f >> 4, c4 = f & 15;
            *(float4*)&Bs[buf][row][c4*4] = rb[i];
        }
    };

    ldg_tile(0);
    sts_tile(0);
    __syncthreads();

    const int KT = KK/BK;
    int buf = 0;
    for (int kt = 0; kt < KT; kt++){
        if (kt + 1 < KT) ldg_tile((kt+1)*BK);
        #pragma unroll
        for (int k = 0; k < BK; k++){
            float4 a0 = *(const float4*)&As[buf][k][ty*8];
            float4 a1 = *(const float4*)&As[buf][k][ty*8+4];
            float4 b0 = *(const float4*)&Bs[buf][k][tx*4];
            float a[8] = {a0.x,a0.y,a0.z,a0.w,a1.x,a1.y,a1.z,a1.w};
            float b[4] = {b0.x,b0.y,b0.z,b0.w};
            #pragma unroll
            for (int i = 0; i < 8; i++)
                #pragma unroll
                for (int j = 0; j < 4; j++)
                    acc[i][j] += a[i]*b[j];
        }
        if (kt + 1 < KT){
            sts_tile(buf^1);
            __syncthreads();
            buf ^= 1;
        }
    }

    #pragma unroll
    for (int i = 0; i < 8; i++){
        int gr = bm*BM + ty*8 + i;
        #pragma unroll
        for (int j = 0; j < 4; j++){
            int gc = bn*BN + tx*4 + j;
            C[gr*N + gc] = acc[i][j] + bias[gc];
        }
    }
}

// ============ fp16 mma.sync GEMM, 4-stage cp.async, XOR swizzle =============
#define STG16 8192
#define OFF_BH (4*STG16)          // 32768
#define OFF_SB2 (8*STG16)         // 65536
#define SMEM_MMA (OFF_SB2 + 512)

__global__ void __launch_bounds__(256) gemmMMA_kernel(const float* __restrict__ b2,
                                                      const float* __restrict__ x){
    extern __shared__ char smem[];
    const uint32_t sb = smem_u32(smem);
    float* sbias = (float*)(smem + OFF_SB2);

    const int tid  = threadIdx.x;
    const int lane = tid & 31;
    const int wid  = tid >> 5;
    const int wm   = wid >> 2;
    const int wn   = wid & 3;
    const int bn   = blockIdx.x;        // 0..5
    const int bm   = blockIdx.y;        // 0..729

    if (tid < 128) sbias[tid] = b2[bn*128 + tid];

    const __half* Asrc = g_hiddenH + (size_t)bm*128*HID;
    const __half* Bsrc = g_w2tH    + (size_t)bn*128*HID;

    auto load_stage = [&](int kt, int st){
        uint32_t ab = sb + st*STG16;
        uint32_t bb = sb + OFF_BH + st*STG16;
        #pragma unroll
        for (int i = 0; i < 2; i++){
            int task = tid + i*256;
            int row = task >> 2, q = task & 3;
            uint32_t col = (uint32_t)(q*16) ^ (uint32_t)(((row>>1)&3)<<4);
            cpa16(ab + row*64 + col, Asrc + (size_t)row*HID + kt*32 + q*8);
        }
        #pragma unroll
        for (int i = 0; i < 2; i++){
            int task = tid + i*256;
            int row = task >> 2, q = task & 3;
            uint32_t col = (uint32_t)(q*16) ^ (uint32_t)(((row>>1)&3)<<4);
            cpa16(bb + row*64 + col, Bsrc + (size_t)row*HID + kt*32 + q*8);
        }
        CP_COMMIT();
    };

    float acc[4][4][4];
    #pragma unroll
    for (int i = 0; i < 4; i++)
        #pragma unroll
        for (int j = 0; j < 4; j++)
            #pragma unroll
            for (int k = 0; k < 4; k++) acc[i][j][k] = 0.0f;

    const int arow = lane & 15;
    const uint32_t acb = (lane & 16) ? 16u : 0u;
    const uint32_t aswz = (uint32_t)(((arow>>1)&3)<<4);
    const int brow = (lane & 7) | ((lane & 16) >> 1);
    const uint32_t bcb = (lane & 8) ? 16u : 0u;
    const uint32_t bswz = (uint32_t)(((brow>>1)&3)<<4);
    uint32_t aoff[4], boff[2];
    #pragma unroll
    for (int mi = 0; mi < 4; mi++) aoff[mi] = (uint32_t)((wm*64 + mi*16 + arow)*64);
    #pragma unroll
    for (int p = 0; p < 2; p++)   boff[p]  = (uint32_t)((wn*32 + p*16 + brow)*64);

    load_stage(0, 0); load_stage(1, 1); load_stage(2, 2);

    #pragma unroll 1
    for (int kt = 0; kt < 8; kt++){
        if (kt < 6) cpwait<2>(); else if (kt == 6) cpwait<1>(); else cpwait<0>();
        __syncthreads();
        if (kt + 3 < 8) load_stage(kt+3, (kt+3)&3);

        uint32_t abase = sb + (kt&3)*STG16;
        uint32_t bbase = sb + OFF_BH + (kt&3)*STG16;
        #pragma unroll
        for (int ks = 0; ks < 2; ks++){
            uint32_t acol = (acb + (uint32_t)(ks*32)) ^ aswz;
            uint32_t bcol = (bcb + (uint32_t)(ks*32)) ^ bswz;
            uint32_t aF[4][4];
            uint32_t bF[4][2];
            LDSM_X4(aF[0][0],aF[0][1],aF[0][2],aF[0][3], abase + aoff[0] + acol);
            LDSM_X4(aF[1][0],aF[1][1],aF[1][2],aF[1][3], abase + aoff[1] + acol);
            LDSM_X4(aF[2][0],aF[2][1],aF[2][2],aF[2][3], abase + aoff[2] + acol);
            LDSM_X4(aF[3][0],aF[3][1],aF[3][2],aF[3][3], abase + aoff[3] + acol);
            LDSM_X4(bF[0][0],bF[0][1],bF[1][0],bF[1][1], bbase + boff[0] + bcol);
            LDSM_X4(bF[2][0],bF[2][1],bF[3][0],bF[3][1], bbase + boff[1] + bcol);
            #pragma unroll
            for (int mi = 0; mi < 4; mi++)
                #pragma unroll
                for (int ni = 0; ni < 4; ni++)
                    MMA_F16(acc[mi][ni][0],acc[mi][ni][1],acc[mi][ni][2],acc[mi][ni][3],
                            aF[mi][0],aF[mi][1],aF[mi][2],aF[mi][3],
                            bF[ni][0],bF[ni][1]);
        }
    }

    // ---- fused epilogue: bias + activation -> fp16 Pl/Ev/Vm ----
    const int grp = bn >> 1;
    const int h0  = (bn & 1)*128;
    __half* outp = (grp == 0) ? g_PlH : (grp == 1) ? g_EvH : g_VmH;
    const int qr = lane >> 2, qc = (lane & 3)*2;

    #pragma unroll
    for (int mi = 0; mi < 4; mi++){
        int r0 = bm*128 + wm*64 + mi*16 + qr;
        int r1 = r0 + 8;
        float s0 = 0.0f, s1 = 0.0f;
        if (grp == 0){ s0 = g_pfrac[r0]; s1 = g_pfrac[r1]; }
        if (grp == 1){ s0 = x[r0*6 + 1]; s1 = x[r1*6 + 1]; }
        #pragma unroll
        for (int ni = 0; ni < 4; ni++){
            int cl = wn*32 + ni*8 + qc;
            float b0v = sbias[cl], b1v = sbias[cl+1];
            float v0 = acc[mi][ni][0] + b0v;
            float v1 = acc[mi][ni][1] + b1v;
            float v2 = acc[mi][ni][2] + b0v;
            float v3 = acc[mi][ni][3] + b1v;
            float2 o0, o1;
            if (grp == 0){
                o0.x = s0*fminf(fmaxf(v0*(2.0f/6.0f)+0.5f,0.0f),1.0f);
                o0.y = s0*fminf(fmaxf(v1*(2.0f/6.0f)+0.5f,0.0f),1.0f);
                o1.x = s1*fminf(fmaxf(v2*(2.0f/6.0f)+0.5f,0.0f),1.0f);
                o1.y = s1*fminf(fmaxf(v3*(2.0f/6.0f)+0.5f,0.0f),1.0f);
            } else if (grp == 1){
                o0.x = s0*fmaxf(v0,0.0f)*2.0f;
                o0.y = s0*fmaxf(v1,0.0f)*2.0f;
                o1.x = s1*fmaxf(v2,0.0f)*2.0f;
                o1.y = s1*fmaxf(v3,0.0f)*2.0f;
            } else {
                o0.x = expf(v0); o0.y = expf(v1);
                o1.x = expf(v2); o1.y = expf(v3);
            }
            *(half2*)(outp + (size_t)r0*NH + h0 + cl) = __floats2half2_rn(o0.x, o0.y);
            *(half2*)(outp + (size_t)r1*NH + h0 + cl) = __floats2half2_rn(o1.x, o1.y);
        }
    }
}

// ---------------- fcW + fcR activations, one launch --------------------------
__global__ void __launch_bounds__(256) actWR_kernel(){
    int h = threadIdx.x;
    if (blockIdx.x < NS){
        int s = blockIdx.x;
        const float* w = g_w + s*(NH*7);
        float kp = sigf(w[h]);
        float ks = sigf(w[NH+h]);
        float kg = sigf(w[2*NH+h])/10.0f;
        float gp = sigf(w[3*NH+h]);
        float e  = expf(w[4*NH+h]);
        float gL = e*e;
        float qb = fmaxf(w[5*NH+h], 0.0f);
        float gar = w[6*NH+h];

        __shared__ float red[8];
        float m = gar;
        #pragma unroll
        for (int o = 16; o; o >>= 1) m = fmaxf(m, __shfl_xor_sync(0xffffffffu, m, o));
        if ((h & 31) == 0) red[h>>5] = m;
        __syncthreads();
        if (h < 32){
            float v = (h < 8) ? red[h] : -1e30f;
            #pragma unroll
            for (int o = 4; o; o >>= 1) v = fmaxf(v, __shfl_xor_sync(0xffffffffu, v, o));
            if (h == 0) red[0] = v;
        }
        __syncthreads();
        float M = red[0];
        __syncthreads();
        float eg = expf(gar - M);
        float sm = eg;
        #pragma unroll
        for (int o = 16; o; o >>= 1) sm += __shfl_xor_sync(0xffffffffu, sm, o);
        if ((h & 31) == 0) red[h>>5] = sm;
        __syncthreads();
        if (h < 32){
            float v = (h < 8) ? red[h] : 0.0f;
            #pragma unroll
            for (int o = 4; o; o >>= 1) v += __shfl_xor_sync(0xffffffffu, v, o);
            if (h == 0) red[0] = v;
        }
        __syncthreads();
        float S = red[0];

        int ix = s*NH + h;
        g_kp[ix] = kp; g_ks[ix] = ks; g_kg[ix] = kg; g_gp[ix] = gp;
        g_gL[ix] = gL; g_qb[ix] = qb; g_ga[ix] = eg/S;
    } else {
        int s = blockIdx.x - NS;
        const float* rf = g_rfraw + s*(NH*NR) + h*NR;
        float v[NR];
        float m = -1e30f;
        #pragma unroll
        for (int j = 0; j < NR; j++){ v[j] = fmaxf(rf[j], 0.0f); m = fmaxf(m, v[j]); }
        float ssum = 0.0f;
        #pragma unroll
        for (int j = 0; j < NR; j++){ v[j] = expf(v[j]-m); ssum += v[j]; }
        float* out = g_r + s*(NH*NR) + h*NR;
        #pragma unroll
        for (int j = 0; j < NR; j++) out[j] = v[j]/ssum;
    }
}

// ============ fused reservoir scan (PF8, fp16 fluxes) + 16-tap conv =========
__global__ void __launch_bounds__(256) scanconv_kernel(float* __restrict__ out){
    __shared__ float sPs[368];
    __shared__ float sQ[256*33];       // reused as yPart in phase B

    const int s = blockIdx.x, tid = threadIdx.x, h = tid;

    for (int i = tid; i < NT; i += 256) sPs[i] = g_PsT[s*QSTR + i];

    const int idx0 = (s << 8) + h;
    const float kp = g_kp[idx0], ks = g_ks[idx0], kg = g_kg[idx0];
    const float gp = g_gp[idx0], gL = g_gL[idx0], qb = g_qb[idx0];
    __syncthreads();

    float Sf = 0.0f, Ss = 0.0f, Sg = 0.0f;
    const size_t str = (size_t)NS*NH;
    float fl[8], fev[8], fm[8];
    {
        size_t ix = idx0;
        #pragma unroll
        for (int i = 0; i < 8; i++){
            fl[i] = __half2float(g_PlH[ix]);
            fev[i] = __half2float(g_EvH[ix]);
            fm[i] = __half2float(g_VmH[ix]);
            ix += str;
        }
    }
    size_t ixn = (size_t)idx0 + 8*str;

    auto step = [&](int tt, float cfl, float cfev, float cfm){
        float fs = sPs[tt];
        float a  = Sf + fs;
        float qf = fminf(a, cfm);
        Sf = fmaxf(a - cfm, 0.0f);
        float H  = fmaxf(Ss + cfl + qf - cfev, 0.0f);
        float qp = fmaxf(kp*(H - gL), 0.0f);
        float qsa = ks*fminf(H, gL);
        Ss = H - qp - qsa;
        float sgin = Sg + qsa*gp;
        float qg = kg*sgin + qb;
        Sg = (1.0f - kg)*sgin - qb;
        return qp + qsa*(1.0f - gp) + qg;
    };
    auto flush = [&](int t0, int cnt){
        __syncthreads();
        #pragma unroll
        for (int it = 0; it < 32; it++){
            int u = tid + it*256;
            int hh = u >> 5, tt = u & 31;
            if (tt < cnt)
                g_Qt[(size_t)((s<<8)+hh)*QSTR + t0 + tt] = sQ[hh*33 + tt];
        }
        __syncthreads();
    };

    #pragma unroll 1
    for (int tb = 0; tb < 360; tb += 8){
        #pragma unroll
        for (int i = 0; i < 8; i++){
            int tt = tb + i;
            float cfl = fl[i], cfev = fev[i], cfm = fm[i];
            if (tt + 8 < NT){
                fl[i] = __half2float(g_PlH[ixn]);
                fev[i] = __half2float(g_EvH[ixn]);
                fm[i] = __half2float(g_VmH[ixn]);
                ixn += str;
            }
            float q = step(tt, cfl, cfev, cfm);
            sQ[h*33 + (tt & 31)] = q;
            if ((tt & 31) == 31) flush(tt - 31, 32);
        }
    }
    #pragma unroll
    for (int i = 0; i < 5; i++){
        int tt = 360 + i;
        float q = step(tt, fl[i], fev[i], fm[i]);
        sQ[h*33 + (tt & 31)] = q;
    }
    flush(352, 13);

    // ---- phase B: conv + ga-weighted reduce over h ----
    const int w = tid >> 5, lane = tid & 31;
    const int t0 = lane*11;
    float y[11];
    #pragma unroll
    for (int i = 0; i < 11; i++) y[i] = 0.0f;

    for (int hh = 0; hh < 32; hh++){
        int base = (s << 8) + w*32 + hh;
        float gah = g_ga[base];
        const float* rp = g_r + (size_t)base*NR;
        float c[16];
        #pragma unroll
        for (int j = 0; j < 16; j++) c[j] = gah*rp[j];
        const float* qp2 = g_Qt + (size_t)base*QSTR + t0;
        float q[26];
        #pragma unroll
        for (int u = 0; u < 26; u++) q[u] = (t0 + u < NT) ? qp2[u] : 0.0f;
        #pragma unroll
        for (int i = 0; i < 11; i++){
            float acc = y[i];
            #pragma unroll
            for (int j = 0; j < 16; j++) acc += c[j]*q[i+j];
            y[i] = acc;
        }
    }
    float* yP = sQ;
    #pragma unroll
    for (int i = 0; i < 11; i++) yP[w*352 + t0 + i] = y[i];
    __syncthreads();
    for (int t = tid; t < TOUT; t += 256){
        float acc = 0.0f;
        #pragma unroll
        for (int w2 = 0; w2 < 8; w2++) acc += yP[w2*352 + t];
        out[t*NS + s] = acc;
    }
}

// ---------------- launch ----------------------------------------------------
extern "C" void kernel_launch(void* const* d_in, const int* in_sizes, int n_in,
                              void* d_out, int out_size){
    const float* x      = (const float*)d_in[0];
    const float* xc     = (const float*)d_in[1];
    const float* fcW_w1 = (const float*)d_in[2];
    const float* fcW_b1 = (const float*)d_in[3];
    const float* fcW_w2 = (const float*)d_in[4];
    const float* fcW_b2 = (const float*)d_in[5];
    const float* fcT_w1 = (const float*)d_in[6];
    const float* fcT_b1 = (const float*)d_in[7];
    const float* fcT_w2 = (const float*)d_in[8];
    const float* fcT_b2 = (const float*)d_in[9];
    const float* fcR_w1 = (const float*)d_in[10];
    const float* fcR_b1 = (const float*)d_in[11];
    const float* fcR_w2 = (const float*)d_in[12];
    const float* fcR_b2 = (const float*)d_in[13];
    float* out = (float*)d_out;

    cudaFuncSetAttribute(gemmMMA_kernel, cudaFuncAttributeMaxDynamicSharedMemorySize, SMEM_MMA);

    setup_kernel<<<365+192+768, 256>>>(x, xc, fcT_w2, fcW_w1, fcW_b1, fcR_w1, fcR_b1, fcT_w1, fcT_b1);
    gemmWR_kernel<<<dim3(92, 2), 256>>>(fcW_w2, fcW_b2, fcR_w2, fcR_b2);
    actWR_kernel<<<2*NS, 256>>>();
    hiddenT_kernel<<<dim3(NS, 4), 128>>>(x, fcT_w1);
    gemmMMA_kernel<<<dim3(6, MTILES), 256, SMEM_MMA>>>(fcT_b2, x);
    scanconv_kernel<<<NS, 256>>>(out);
}

// round 7
// speedup vs baseline: 1.3691x; 1.3691x over previous
#include <cuda_runtime.h>
#include <cuda_fp16.h>
#include <cstdint>
#include <math.h>

#define NT  365
#define NS  256
#define NH  256
#define NG  32
#define NR  16
#define HID 256
#define NTS (NT*NS)          // 93440
#define TOUT (NT-NR+1)       // 350
#define MTILES 730           // 93440/128
#define QSTR 372             // padded time stride for transposed Q
#define TCHUNK 92            // hiddenT t-chunk (4*92=368 >= 365)

// ---------------- scratch (device globals) ----------------------------------
__device__ __half g_hiddenH[NTS*HID]; // fcT layer-1 output (tanh, fp16)
__device__ float g_Pl[NTS*NH];
__device__ float g_Ev[NTS*NH];
__device__ float g_Vm[NTS*NH];
__device__ float g_Qt[NS*NH*QSTR];    // time-contiguous Q
__device__ float g_hidW[NS*HID];
__device__ float g_hidR[NS*HID];
__device__ float g_baseT[NS*HID];
__device__ float g_w[NS*NH*7];
__device__ float g_rfraw[NS*NH*NR];
__device__ float g_kp[NS*NH], g_ks[NS*NH], g_kg[NS*NH], g_gp[NS*NH];
__device__ float g_gL[NS*NH], g_qb[NS*NH], g_ga[NS*NH];
__device__ float g_r[NS*NH*NR];
__device__ float g_PsT[NS*QSTR];      // snowfall, transposed [s][t]
__device__ float g_pfrac[NTS];
__device__ __half g_w2tH[768*HID];    // fcT_w2^T, fp16

__device__ __forceinline__ float sigf(float x){ return 1.0f/(1.0f+expf(-x)); }
__device__ __forceinline__ float tanha(float x){
    float y; asm("tanh.approx.f32 %0, %1;" : "=f"(y) : "f"(x)); return y;
}

__device__ __forceinline__ uint32_t smem_u32(const void* p){
    uint32_t a;
    asm("{ .reg .u64 t; cvta.to.shared.u64 t, %1; cvt.u32.u64 %0, t; }" : "=r"(a) : "l"(p));
    return a;
}
__device__ __forceinline__ void cpa16(uint32_t dst, const void* src){
    asm volatile("cp.async.cg.shared.global [%0], [%1], 16;" :: "r"(dst), "l"(src) : "memory");
}
#define CP_COMMIT() asm volatile("cp.async.commit_group;" ::: "memory")
template<int N> __device__ __forceinline__ void cpwait(){
    asm volatile("cp.async.wait_group %0;" :: "n"(N) : "memory");
}
#define LDSM_X4(r0,r1,r2,r3,addr) \
    asm volatile("ldmatrix.sync.aligned.m8n8.x4.shared.b16 {%0,%1,%2,%3}, [%4];" \
        : "=r"(r0),"=r"(r1),"=r"(r2),"=r"(r3) : "r"(addr))
#define MMA_F16(c0,c1,c2,c3,a0,a1,a2,a3,b0,b1) \
    asm volatile("mma.sync.aligned.m16n8k16.row.col.f32.f16.f16.f32 " \
        "{%0,%1,%2,%3}, {%4,%5,%6,%7}, {%8,%9}, {%0,%1,%2,%3};" \
        : "+f"(c0),"+f"(c1),"+f"(c2),"+f"(c3) \
        : "r"(a0),"r"(a1),"r"(a2),"r"(a3), "r"(b0),"r"(b1))

// ============ setup: prep + transposeB(fp16) + layer1 in one launch =========
__global__ void __launch_bounds__(256) setup_kernel(
        const float* __restrict__ x, const float* __restrict__ xc,
        const float* __restrict__ w2,
        const float* __restrict__ wW1, const float* __restrict__ bW1,
        const float* __restrict__ wR1, const float* __restrict__ bR1,
        const float* __restrict__ wT1, const float* __restrict__ bT1){
    __shared__ float sh[32*33];
    int bid = blockIdx.x, tid = threadIdx.x;
    if (bid < 365){
        int i = bid*256 + tid;
        float P  = x[i*6+0];
        float T1 = x[i*6+2];
        float T2 = x[i*6+3];
        float ratio = (T1+T2)/(T2-T1);
        ratio = fminf(fmaxf(ratio,-1.0f),1.0f);
        float vf = acosf(ratio)/3.1415f;
        if (T1 >= 0.0f) vf = 0.0f;
        if (T2 <= 0.0f) vf = 1.0f;
        int s = i & 255, t = i >> 8;
        g_PsT[s*QSTR + t] = P*vf;
        g_pfrac[i] = P*(1.0f-vf);
    } else if (bid < 365+192){
        int tb = bid - 365;
        int nb = (tb % 24)*32, kb = (tb / 24)*32;
        int tx = tid & 31, ty = tid >> 5;
        #pragma unroll
        for (int r = 0; r < 32; r += 8)
            sh[(ty+r)*33 + tx] = w2[(kb+ty+r)*768 + nb + tx];
        __syncthreads();
        #pragma unroll
        for (int r = 0; r < 32; r += 8)
            g_w2tH[(nb+ty+r)*HID + kb + tx] = __float2half(sh[tx*33 + ty + r]);
    } else {
        int lb = bid - 557;
        int s = lb & 255, mode = lb >> 8, h = tid;
        float* xs = sh;
        if (h < NG) xs[h] = xc[s*NG + h];
        __syncthreads();
        const float* w; const float* b; float* out; bool dotanh;
        if (mode == 0){ w = wW1;      b = bW1; out = g_hidW;  dotanh = true;  }
        else if (mode == 1){ w = wR1; b = bR1; out = g_hidR;  dotanh = true;  }
        else { w = wT1 + 6*HID;       b = bT1; out = g_baseT; dotanh = false; }
        float acc = b[h];
        #pragma unroll
        for (int g = 0; g < NG; g++) acc += xs[g]*w[g*HID + h];
        out[s*HID + h] = dotanh ? tanhf(acc) : acc;
    }
}

// ---------------- fcT layer-1: block per (s, t-chunk), regs-resident weights -
__global__ void __launch_bounds__(128) hiddenT_kernel(const float* __restrict__ x,
                                                      const float* __restrict__ wT1){
    const int s = blockIdx.x;
    const int t0 = blockIdx.y*TCHUNK;
    const int t1 = min(t0 + TCHUNK, NT);
    const int nt = t1 - t0;
    const int hl = threadIdx.x, hh = hl*2;

    float w0[6], w1[6];
    #pragma unroll
    for (int i = 0; i < 6; i++){
        w0[i] = wT1[i*HID + hh];
        w1[i] = wT1[i*HID + hh + 1];
    }
    const float b0 = g_baseT[s*HID + hh];
    const float b1 = g_baseT[s*HID + hh + 1];

    __shared__ float sx[TCHUNK*6];
    for (int u = hl; u < nt*6; u += 128){
        int j = u/6, i = u - j*6;
        sx[u] = x[(size_t)(t0 + j)*(NS*6) + s*6 + i];
    }
    __syncthreads();

    __half* dst = g_hiddenH + ((size_t)(t0*NS + s))*HID + hh;
    #pragma unroll 4
    for (int j = 0; j < nt; j++){
        const float* xv = sx + j*6;
        float a0 = b0, a1 = b1;
        #pragma unroll
        for (int i = 0; i < 6; i++){
            float f = xv[i];
            a0 += f*w0[i];
            a1 += f*w1[i];
        }
        *(half2*)(dst + (size_t)j*(NS*HID)) = __floats2half2_rn(tanha(a0), tanha(a1));
    }
}

// ---------------- combined small SIMT GEMMs (fcW + fcR layer 2) -------------
#define BM 128
#define BN 64
#define BK 32
#define KK 256

__global__ void __launch_bounds__(256) gemmWR_kernel(
        const float* __restrict__ Wb, const float* __restrict__ Wbias,
        const float* __restrict__ Rb, const float* __restrict__ Rbias){
    const float* A; float* C; const float* B; const float* bias; int N; int bn;
    if (blockIdx.x < 28){ A = g_hidW; C = g_w;     B = Wb; bias = Wbias; N = NH*7;  bn = blockIdx.x; }
    else                { A = g_hidR; C = g_rfraw; B = Rb; bias = Rbias; N = NH*NR; bn = blockIdx.x - 28; }

    __shared__ float As[2][BK][BM];
    __shared__ float Bs[2][BK][BN];

    const int tid = threadIdx.x;
    const int tx  = tid & 15;
    const int ty  = tid >> 4;
    const int bm  = blockIdx.y;

    const float* Ag = A + bm*BM*KK;
    const float* Bg = B + bn*BN;

    float acc[8][4];
    #pragma unroll
    for (int i = 0; i < 8; i++)
        #pragma unroll
        for (int j = 0; j < 4; j++) acc[i][j] = 0.0f;

    float4 ra[4], rb[2];
    auto ldg_tile = [&](int k0){
        #pragma unroll
        for (int i = 0; i < 4; i++){
            int f = tid + i*256;
            int row = f >> 3, c4 = f & 7;
            ra[i] = *(const float4*)(Ag + row*KK + k0 + c4*4);
        }
        #pragma unroll
        for (int i = 0; i < 2; i++){
            int f = tid + i*256;
            int row = f >> 4, c4 = f & 15;
            rb[i] = *(const float4*)(Bg + (k0 + row)*N + c4*4);
        }
    };
    auto sts_tile = [&](int buf){
        #pragma unroll
        for (int i = 0; i < 4; i++){
            int f = tid + i*256;
            int row = f >> 3, c4 = f & 7;
            As[buf][c4*4+0][row] = ra[i].x;
            As[buf][c4*4+1][row] = ra[i].y;
            As[buf][c4*4+2][row] = ra[i].z;
            As[buf][c4*4+3][row] = ra[i].w;
        }
        #pragma unroll
        for (int i = 0; i < 2; i++){
            int f = tid + i*256;
            int row = f >> 4, c4 = f & 15;
            *(float4*)&Bs[buf][row][c4*4] = rb[i];
        }
    };

    ldg_tile(0);
    sts_tile(0);
    __syncthreads();

    const int KT = KK/BK;
    int buf = 0;
    for (int kt = 0; kt < KT; kt++){
        if (kt + 1 < KT) ldg_tile((kt+1)*BK);
        #pragma unroll
        for (int k = 0; k < BK; k++){
            float4 a0 = *(const float4*)&As[buf][k][ty*8];
            float4 a1 = *(const float4*)&As[buf][k][ty*8+4];
            float4 b0 = *(const float4*)&Bs[buf][k][tx*4];
            float a[8] = {a0.x,a0.y,a0.z,a0.w,a1.x,a1.y,a1.z,a1.w};
            float b[4] = {b0.x,b0.y,b0.z,b0.w};
            #pragma unroll
            for (int i = 0; i < 8; i++)
                #pragma unroll
                for (int j = 0; j < 4; j++)
                    acc[i][j] += a[i]*b[j];
        }
        if (kt + 1 < KT){
            sts_tile(buf^1);
            __syncthreads();
            buf ^= 1;
        }
    }

    #pragma unroll
    for (int i = 0; i < 8; i++){
        int gr = bm*BM + ty*8 + i;
        #pragma unroll
        for (int j = 0; j < 4; j++){
            int gc = bn*BN + tx*4 + j;
            C[gr*N + gc] = acc[i][j] + bias[gc];
        }
    }
}

// ============ fp16 mma.sync GEMM, 4-stage cp.async, XOR swizzle =============
#define STG16 8192
#define OFF_BH (4*STG16)          // 32768
#define OFF_SB2 (8*STG16)         // 65536
#define SMEM_MMA (OFF_SB2 + 512)

__global__ void __launch_bounds__(256) gemmMMA_kernel(const float* __restrict__ b2,
                                                      const float* __restrict__ x){
    extern __shared__ char smem[];
    const uint32_t sb = smem_u32(smem);
    float* sbias = (float*)(smem + OFF_SB2);

    const int tid  = threadIdx.x;
    const int lane = tid & 31;
    const int wid  = tid >> 5;
    const int wm   = wid >> 2;
    const int wn   = wid & 3;
    const int bn   = blockIdx.x;        // 0..5
    const int bm   = blockIdx.y;        // 0..729

    if (tid < 128) sbias[tid] = b2[bn*128 + tid];

    const __half* Asrc = g_hiddenH + (size_t)bm*128*HID;
    const __half* Bsrc = g_w2tH    + (size_t)bn*128*HID;

    auto load_stage = [&](int kt, int st){
        uint32_t ab = sb + st*STG16;
        uint32_t bb = sb + OFF_BH + st*STG16;
        #pragma unroll
        for (int i = 0; i < 2; i++){
            int task = tid + i*256;
            int row = task >> 2, q = task & 3;
            uint32_t col = (uint32_t)(q*16) ^ (uint32_t)(((row>>1)&3)<<4);
            cpa16(ab + row*64 + col, Asrc + (size_t)row*HID + kt*32 + q*8);
        }
        #pragma unroll
        for (int i = 0; i < 2; i++){
            int task = tid + i*256;
            int row = task >> 2, q = task & 3;
            uint32_t col = (uint32_t)(q*16) ^ (uint32_t)(((row>>1)&3)<<4);
            cpa16(bb + row*64 + col, Bsrc + (size_t)row*HID + kt*32 + q*8);
        }
        CP_COMMIT();
    };

    float acc[4][4][4];
    #pragma unroll
    for (int i = 0; i < 4; i++)
        #pragma unroll
        for (int j = 0; j < 4; j++)
            #pragma unroll
            for (int k = 0; k < 4; k++) acc[i][j][k] = 0.0f;

    const int arow = lane & 15;
    const uint32_t acb = (lane & 16) ? 16u : 0u;
    const uint32_t aswz = (uint32_t)(((arow>>1)&3)<<4);
    const int brow = (lane & 7) | ((lane & 16) >> 1);
    const uint32_t bcb = (lane & 8) ? 16u : 0u;
    const uint32_t bswz = (uint32_t)(((brow>>1)&3)<<4);
    uint32_t aoff[4], boff[2];
    #pragma unroll
    for (int mi = 0; mi < 4; mi++) aoff[mi] = (uint32_t)((wm*64 + mi*16 + arow)*64);
    #pragma unroll
    for (int p = 0; p < 2; p++)   boff[p]  = (uint32_t)((wn*32 + p*16 + brow)*64);

    load_stage(0, 0); load_stage(1, 1); load_stage(2, 2);

    #pragma unroll 1
    for (int kt = 0; kt < 8; kt++){
        if (kt < 6) cpwait<2>(); else if (kt == 6) cpwait<1>(); else cpwait<0>();
        __syncthreads();
        if (kt + 3 < 8) load_stage(kt+3, (kt+3)&3);

        uint32_t abase = sb + (kt&3)*STG16;
        uint32_t bbase = sb + OFF_BH + (kt&3)*STG16;
        #pragma unroll
        for (int ks = 0; ks < 2; ks++){
            uint32_t acol = (acb + (uint32_t)(ks*32)) ^ aswz;
            uint32_t bcol = (bcb + (uint32_t)(ks*32)) ^ bswz;
            uint32_t aF[4][4];
            uint32_t bF[4][2];
            LDSM_X4(aF[0][0],aF[0][1],aF[0][2],aF[0][3], abase + aoff[0] + acol);
            LDSM_X4(aF[1][0],aF[1][1],aF[1][2],aF[1][3], abase + aoff[1] + acol);
            LDSM_X4(aF[2][0],aF[2][1],aF[2][2],aF[2][3], abase + aoff[2] + acol);
            LDSM_X4(aF[3][0],aF[3][1],aF[3][2],aF[3][3], abase + aoff[3] + acol);
            LDSM_X4(bF[0][0],bF[0][1],bF[1][0],bF[1][1], bbase + boff[0] + bcol);
            LDSM_X4(bF[2][0],bF[2][1],bF[3][0],bF[3][1], bbase + boff[1] + bcol);
            #pragma unroll
            for (int mi = 0; mi < 4; mi++)
                #pragma unroll
                for (int ni = 0; ni < 4; ni++)
                    MMA_F16(acc[mi][ni][0],acc[mi][ni][1],acc[mi][ni][2],acc[mi][ni][3],
                            aF[mi][0],aF[mi][1],aF[mi][2],aF[mi][3],
                            bF[ni][0],bF[ni][1]);
        }
    }

    // ---- fused epilogue: bias + activation -> fp32 Pl/Ev/Vm ----
    const int grp = bn >> 1;
    const int h0  = (bn & 1)*128;
    float* outp = (grp == 0) ? g_Pl : (grp == 1) ? g_Ev : g_Vm;
    const int qr = lane >> 2, qc = (lane & 3)*2;

    #pragma unroll
    for (int mi = 0; mi < 4; mi++){
        int r0 = bm*128 + wm*64 + mi*16 + qr;
        int r1 = r0 + 8;
        float s0 = 0.0f, s1 = 0.0f;
        if (grp == 0){ s0 = g_pfrac[r0]; s1 = g_pfrac[r1]; }
        if (grp == 1){ s0 = x[r0*6 + 1]; s1 = x[r1*6 + 1]; }
        #pragma unroll
        for (int ni = 0; ni < 4; ni++){
            int cl = wn*32 + ni*8 + qc;
            float b0v = sbias[cl], b1v = sbias[cl+1];
            float v0 = acc[mi][ni][0] + b0v;
            float v1 = acc[mi][ni][1] + b1v;
            float v2 = acc[mi][ni][2] + b0v;
            float v3 = acc[mi][ni][3] + b1v;
            float2 o0, o1;
            if (grp == 0){
                o0.x = s0*fminf(fmaxf(v0*(2.0f/6.0f)+0.5f,0.0f),1.0f);
                o0.y = s0*fminf(fmaxf(v1*(2.0f/6.0f)+0.5f,0.0f),1.0f);
                o1.x = s1*fminf(fmaxf(v2*(2.0f/6.0f)+0.5f,0.0f),1.0f);
                o1.y = s1*fminf(fmaxf(v3*(2.0f/6.0f)+0.5f,0.0f),1.0f);
            } else if (grp == 1){
                o0.x = s0*fmaxf(v0,0.0f)*2.0f;
                o0.y = s0*fmaxf(v1,0.0f)*2.0f;
                o1.x = s1*fmaxf(v2,0.0f)*2.0f;
                o1.y = s1*fmaxf(v3,0.0f)*2.0f;
            } else {
                o0.x = expf(v0); o0.y = expf(v1);
                o1.x = expf(v2); o1.y = expf(v3);
            }
            *(float2*)(outp + (size_t)r0*NH + h0 + cl) = o0;
            *(float2*)(outp + (size_t)r1*NH + h0 + cl) = o1;
        }
    }
}

// ---------------- fcW + fcR activations, one launch --------------------------
__global__ void __launch_bounds__(256) actWR_kernel(){
    int h = threadIdx.x;
    if (blockIdx.x < NS){
        int s = blockIdx.x;
        const float* w = g_w + s*(NH*7);
        float kp = sigf(w[h]);
        float ks = sigf(w[NH+h]);
        float kg = sigf(w[2*NH+h])/10.0f;
        float gp = sigf(w[3*NH+h]);
        float e  = expf(w[4*NH+h]);
        float gL = e*e;
        float qb = fmaxf(w[5*NH+h], 0.0f);
        float gar = w[6*NH+h];

        __shared__ float red[8];
        float m = gar;
        #pragma unroll
        for (int o = 16; o; o >>= 1) m = fmaxf(m, __shfl_xor_sync(0xffffffffu, m, o));
        if ((h & 31) == 0) red[h>>5] = m;
        __syncthreads();
        if (h < 32){
            float v = (h < 8) ? red[h] : -1e30f;
            #pragma unroll
            for (int o = 4; o; o >>= 1) v = fmaxf(v, __shfl_xor_sync(0xffffffffu, v, o));
            if (h == 0) red[0] = v;
        }
        __syncthreads();
        float M = red[0];
        __syncthreads();
        float eg = expf(gar - M);
        float sm = eg;
        #pragma unroll
        for (int o = 16; o; o >>= 1) sm += __shfl_xor_sync(0xffffffffu, sm, o);
        if ((h & 31) == 0) red[h>>5] = sm;
        __syncthreads();
        if (h < 32){
            float v = (h < 8) ? red[h] : 0.0f;
            #pragma unroll
            for (int o = 4; o; o >>= 1) v += __shfl_xor_sync(0xffffffffu, v, o);
            if (h == 0) red[0] = v;
        }
        __syncthreads();
        float S = red[0];

        int ix = s*NH + h;
        g_kp[ix] = kp; g_ks[ix] = ks; g_kg[ix] = kg; g_gp[ix] = gp;
        g_gL[ix] = gL; g_qb[ix] = qb; g_ga[ix] = eg/S;
    } else {
        int s = blockIdx.x - NS;
        const float* rf = g_rfraw + s*(NH*NR) + h*NR;
        float v[NR];
        float m = -1e30f;
        #pragma unroll
        for (int j = 0; j < NR; j++){ v[j] = fmaxf(rf[j], 0.0f); m = fmaxf(m, v[j]); }
        float ssum = 0.0f;
        #pragma unroll
        for (int j = 0; j < NR; j++){ v[j] = expf(v[j]-m); ssum += v[j]; }
        float* out = g_r + s*(NH*NR) + h*NR;
        #pragma unroll
        for (int j = 0; j < NR; j++) out[j] = v[j]/ssum;
    }
}

// ============ fused reservoir scan (PF8, transposed Q) + 16-tap conv ========
__global__ void __launch_bounds__(256) scanconv_kernel(float* __restrict__ out){
    __shared__ float sPs[368];
    __shared__ float sQ[256*33];       // reused as yPart in phase B

    const int s = blockIdx.x, tid = threadIdx.x, h = tid;

    for (int i = tid; i < NT; i += 256) sPs[i] = g_PsT[s*QSTR + i];

    const int idx0 = (s << 8) + h;
    const float kp = g_kp[idx0], ks = g_ks[idx0], kg = g_kg[idx0];
    const float gp = g_gp[idx0], gL = g_gL[idx0], qb = g_qb[idx0];
    __syncthreads();

    float Sf = 0.0f, Ss = 0.0f, Sg = 0.0f;
    const size_t str = (size_t)NS*NH;
    float fl[8], fev[8], fm[8];
    {
        size_t ix = idx0;
        #pragma unroll
        for (int i = 0; i < 8; i++){
            fl[i] = g_Pl[ix]; fev[i] = g_Ev[ix]; fm[i] = g_Vm[ix];
            ix += str;
        }
    }
    size_t ixn = (size_t)idx0 + 8*str;

    auto step = [&](int tt, float cfl, float cfev, float cfm){
        float fs = sPs[tt];
        float a  = Sf + fs;
        float qf = fminf(a, cfm);
        Sf = fmaxf(a - cfm, 0.0f);
        float H  = fmaxf(Ss + cfl + qf - cfev, 0.0f);
        float qp = fmaxf(kp*(H - gL), 0.0f);
        float qsa = ks*fminf(H, gL);
        Ss = H - qp - qsa;
        float sgin = Sg + qsa*gp;
        float qg = kg*sgin + qb;
        Sg = (1.0f - kg)*sgin - qb;
        return qp + qsa*(1.0f - gp) + qg;
    };
    auto flush = [&](int t0, int cnt){
        __syncthreads();
        #pragma unroll
        for (int it = 0; it < 32; it++){
            int u = tid + it*256;
            int hh = u >> 5, tt = u & 31;
            if (tt < cnt)
                g_Qt[(size_t)((s<<8)+hh)*QSTR + t0 + tt] = sQ[hh*33 + tt];
        }
        __syncthreads();
    };

    #pragma unroll 1
    for (int tb = 0; tb < 360; tb += 8){
        #pragma unroll
        for (int i = 0; i < 8; i++){
            int tt = tb + i;
            float cfl = fl[i], cfev = fev[i], cfm = fm[i];
            if (tt + 8 < NT){
                fl[i] = g_Pl[ixn]; fev[i] = g_Ev[ixn]; fm[i] = g_Vm[ixn];
                ixn += str;
            }
            float q = step(tt, cfl, cfev, cfm);
            sQ[h*33 + (tt & 31)] = q;
            if ((tt & 31) == 31) flush(tt - 31, 32);
        }
    }
    #pragma unroll
    for (int i = 0; i < 5; i++){
        int tt = 360 + i;
        float q = step(tt, fl[i], fev[i], fm[i]);
        sQ[h*33 + (tt & 31)] = q;
    }
    flush(352, 13);

    // ---- phase B: conv + ga-weighted reduce over h ----
    const int w = tid >> 5, lane = tid & 31;
    const int t0 = lane*11;
    float y[11];
    #pragma unroll
    for (int i = 0; i < 11; i++) y[i] = 0.0f;

    for (int hh = 0; hh < 32; hh++){
        int base = (s << 8) + w*32 + hh;
        float gah = g_ga[base];
        const float* rp = g_r + (size_t)base*NR;
        float c[16];
        #pragma unroll
        for (int j = 0; j < 16; j++) c[j] = gah*rp[j];
        const float* qp2 = g_Qt + (size_t)base*QSTR + t0;
        float q[26];
        #pragma unroll
        for (int u = 0; u < 26; u++) q[u] = (t0 + u < NT) ? qp2[u] : 0.0f;
        #pragma unroll
        for (int i = 0; i < 11; i++){
            float acc = y[i];
            #pragma unroll
            for (int j = 0; j < 16; j++) acc += c[j]*q[i+j];
            y[i] = acc;
        }
    }
    float* yP = sQ;
    #pragma unroll
    for (int i = 0; i < 11; i++) yP[w*352 + t0 + i] = y[i];
    __syncthreads();
    for (int t = tid; t < TOUT; t += 256){
        float acc = 0.0f;
        #pragma unroll
        for (int w2 = 0; w2 < 8; w2++) acc += yP[w2*352 + t];
        out[t*NS + s] = acc;
    }
}

// ---------------- launch ----------------------------------------------------
extern "C" void kernel_launch(void* const* d_in, const int* in_sizes, int n_in,
                              void* d_out, int out_size){
    const float* x      = (const float*)d_in[0];
    const float* xc     = (const float*)d_in[1];
    const float* fcW_w1 = (const float*)d_in[2];
    const float* fcW_b1 = (const float*)d_in[3];
    const float* fcW_w2 = (const float*)d_in[4];
    const float* fcW_b2 = (const float*)d_in[5];
    const float* fcT_w1 = (const float*)d_in[6];
    const float* fcT_b1 = (const float*)d_in[7];
    const float* fcT_w2 = (const float*)d_in[8];
    const float* fcT_b2 = (const float*)d_in[9];
    const float* fcR_w1 = (const float*)d_in[10];
    const float* fcR_b1 = (const float*)d_in[11];
    const float* fcR_w2 = (const float*)d_in[12];
    const float* fcR_b2 = (const float*)d_in[13];
    float* out = (float*)d_out;

    cudaFuncSetAttribute(gemmMMA_kernel, cudaFuncAttributeMaxDynamicSharedMemorySize, SMEM_MMA);

    setup_kernel<<<365+192+768, 256>>>(x, xc, fcT_w2, fcW_w1, fcW_b1, fcR_w1, fcR_b1, fcT_w1, fcT_b1);
    gemmWR_kernel<<<dim3(92, 2), 256>>>(fcW_w2, fcW_b2, fcR_w2, fcR_b2);
    actWR_kernel<<<2*NS, 256>>>();
    hiddenT_kernel<<<dim3(NS, 4), 128>>>(x, fcT_w1);
    gemmMMA_kernel<<<dim3(6, MTILES), 256, SMEM_MMA>>>(fcT_b2, x);
    scanconv_kernel<<<NS, 256>>>(out);
}

// round 8
// speedup vs baseline: 1.5204x; 1.1105x over previous
#include <cuda_runtime.h>
#include <cuda_fp16.h>
#include <cstdint>
#include <math.h>

#define NT  365
#define NS  256
#define NH  256
#define NG  32
#define NR  16
#define HID 256
#define NTS (NT*NS)          // 93440
#define TOUT (NT-NR+1)       // 350
#define MTILES 730           // 93440/128
#define QSTR 372             // padded time stride for PsT
#define TCHUNK 92            // hiddenT t-chunk (4*92=368 >= 365)

// ---------------- scratch (device globals) ----------------------------------
__device__ __half g_hiddenH[NTS*HID]; // fcT layer-1 output (tanh, fp16)
__device__ float g_Pl[NTS*NH];
__device__ float g_Ev[NTS*NH];
__device__ float g_Vm[NTS*NH];
__device__ float g_hidW[NS*HID];
__device__ float g_hidR[NS*HID];
__device__ float g_baseT[NS*HID];
__device__ float g_w[NS*NH*7];
__device__ float g_rfraw[NS*NH*NR];
__device__ float g_kp[NS*NH], g_ks[NS*NH], g_kg[NS*NH], g_gp[NS*NH];
__device__ float g_gL[NS*NH], g_qb[NS*NH], g_ga[NS*NH];
__device__ float g_r[NS*NH*NR];
__device__ float g_PsT[NS*QSTR];      // snowfall, transposed [s][t]
__device__ float g_pfrac[NTS];
__device__ __half g_w2tH[768*HID];    // fcT_w2^T, fp16

__device__ __forceinline__ float sigf(float x){ return 1.0f/(1.0f+expf(-x)); }
__device__ __forceinline__ float tanha(float x){
    float y; asm("tanh.approx.f32 %0, %1;" : "=f"(y) : "f"(x)); return y;
}

__device__ __forceinline__ uint32_t smem_u32(const void* p){
    uint32_t a;
    asm("{ .reg .u64 t; cvta.to.shared.u64 t, %1; cvt.u32.u64 %0, t; }" : "=r"(a) : "l"(p));
    return a;
}
__device__ __forceinline__ void cpa16(uint32_t dst, const void* src){
    asm volatile("cp.async.cg.shared.global [%0], [%1], 16;" :: "r"(dst), "l"(src) : "memory");
}
#define CP_COMMIT() asm volatile("cp.async.commit_group;" ::: "memory")
template<int N> __device__ __forceinline__ void cpwait(){
    asm volatile("cp.async.wait_group %0;" :: "n"(N) : "memory");
}
#define LDSM_X4(r0,r1,r2,r3,addr) \
    asm volatile("ldmatrix.sync.aligned.m8n8.x4.shared.b16 {%0,%1,%2,%3}, [%4];" \
        : "=r"(r0),"=r"(r1),"=r"(r2),"=r"(r3) : "r"(addr))
#define MMA_F16(c0,c1,c2,c3,a0,a1,a2,a3,b0,b1) \
    asm volatile("mma.sync.aligned.m16n8k16.row.col.f32.f16.f16.f32 " \
        "{%0,%1,%2,%3}, {%4,%5,%6,%7}, {%8,%9}, {%0,%1,%2,%3};" \
        : "+f"(c0),"+f"(c1),"+f"(c2),"+f"(c3) \
        : "r"(a0),"r"(a1),"r"(a2),"r"(a3), "r"(b0),"r"(b1))

// ============ setup: prep + transposeB(fp16) + layer1 in one launch =========
__global__ void __launch_bounds__(256) setup_kernel(
        const float* __restrict__ x, const float* __restrict__ xc,
        const float* __restrict__ w2,
        const float* __restrict__ wW1, const float* __restrict__ bW1,
        const float* __restrict__ wR1, const float* __restrict__ bR1,
        const float* __restrict__ wT1, const float* __restrict__ bT1){
    __shared__ float sh[32*33];
    int bid = blockIdx.x, tid = threadIdx.x;
    if (bid < 365){
        int i = bid*256 + tid;
        float P  = x[i*6+0];
        float T1 = x[i*6+2];
        float T2 = x[i*6+3];
        float ratio = (T1+T2)/(T2-T1);
        ratio = fminf(fmaxf(ratio,-1.0f),1.0f);
        float vf = acosf(ratio)/3.1415f;
        if (T1 >= 0.0f) vf = 0.0f;
        if (T2 <= 0.0f) vf = 1.0f;
        int s = i & 255, t = i >> 8;
        g_PsT[s*QSTR + t] = P*vf;
        g_pfrac[i] = P*(1.0f-vf);
    } else if (bid < 365+192){
        int tb = bid - 365;
        int nb = (tb % 24)*32, kb = (tb / 24)*32;
        int tx = tid & 31, ty = tid >> 5;
        #pragma unroll
        for (int r = 0; r < 32; r += 8)
            sh[(ty+r)*33 + tx] = w2[(kb+ty+r)*768 + nb + tx];
        __syncthreads();
        #pragma unroll
        for (int r = 0; r < 32; r += 8)
            g_w2tH[(nb+ty+r)*HID + kb + tx] = __float2half(sh[tx*33 + ty + r]);
    } else {
        int lb = bid - 557;
        int s = lb & 255, mode = lb >> 8, h = tid;
        float* xs = sh;
        if (h < NG) xs[h] = xc[s*NG + h];
        __syncthreads();
        const float* w; const float* b; float* out; bool dotanh;
        if (mode == 0){ w = wW1;      b = bW1; out = g_hidW;  dotanh = true;  }
        else if (mode == 1){ w = wR1; b = bR1; out = g_hidR;  dotanh = true;  }
        else { w = wT1 + 6*HID;       b = bT1; out = g_baseT; dotanh = false; }
        float acc = b[h];
        #pragma unroll
        for (int g = 0; g < NG; g++) acc += xs[g]*w[g*HID + h];
        out[s*HID + h] = dotanh ? tanhf(acc) : acc;
    }
}

// ---------------- fcT layer-1: block per (s, t-chunk), regs-resident weights -
__global__ void __launch_bounds__(128) hiddenT_kernel(const float* __restrict__ x,
                                                      const float* __restrict__ wT1){
    const int s = blockIdx.x;
    const int t0 = blockIdx.y*TCHUNK;
    const int t1 = min(t0 + TCHUNK, NT);
    const int nt = t1 - t0;
    const int hl = threadIdx.x, hh = hl*2;

    float w0[6], w1[6];
    #pragma unroll
    for (int i = 0; i < 6; i++){
        w0[i] = wT1[i*HID + hh];
        w1[i] = wT1[i*HID + hh + 1];
    }
    const float b0 = g_baseT[s*HID + hh];
    const float b1 = g_baseT[s*HID + hh + 1];

    __shared__ float sx[TCHUNK*6];
    for (int u = hl; u < nt*6; u += 128){
        int j = u/6, i = u - j*6;
        sx[u] = x[(size_t)(t0 + j)*(NS*6) + s*6 + i];
    }
    __syncthreads();

    __half* dst = g_hiddenH + ((size_t)(t0*NS + s))*HID + hh;
    #pragma unroll 4
    for (int j = 0; j < nt; j++){
        const float* xv = sx + j*6;
        float a0 = b0, a1 = b1;
        #pragma unroll
        for (int i = 0; i < 6; i++){
            float f = xv[i];
            a0 += f*w0[i];
            a1 += f*w1[i];
        }
        *(half2*)(dst + (size_t)j*(NS*HID)) = __floats2half2_rn(tanha(a0), tanha(a1));
    }
}

// ---------------- combined small SIMT GEMMs (fcW + fcR layer 2) -------------
#define BM 128
#define BN 64
#define BK 32
#define KK 256

__global__ void __launch_bounds__(256) gemmWR_kernel(
        const float* __restrict__ Wb, const float* __restrict__ Wbias,
        const float* __restrict__ Rb, const float* __restrict__ Rbias){
    const float* A; float* C; const float* B; const float* bias; int N; int bn;
    if (blockIdx.x < 28){ A = g_hidW; C = g_w;     B = Wb; bias = Wbias; N = NH*7;  bn = blockIdx.x; }
    else                { A = g_hidR; C = g_rfraw; B = Rb; bias = Rbias; N = NH*NR; bn = blockIdx.x - 28; }

    __shared__ float As[2][BK][BM];
    __shared__ float Bs[2][BK][BN];

    const int tid = threadIdx.x;
    const int tx  = tid & 15;
    const int ty  = tid >> 4;
    const int bm  = blockIdx.y;

    const float* Ag = A + bm*BM*KK;
    const float* Bg = B + bn*BN;

    float acc[8][4];
    #pragma unroll
    for (int i = 0; i < 8; i++)
        #pragma unroll
        for (int j = 0; j < 4; j++) acc[i][j] = 0.0f;

    float4 ra[4], rb[2];
    auto ldg_tile = [&](int k0){
        #pragma unroll
        for (int i = 0; i < 4; i++){
            int f = tid + i*256;
            int row = f >> 3, c4 = f & 7;
            ra[i] = *(const float4*)(Ag + row*KK + k0 + c4*4);
        }
        #pragma unroll
        for (int i = 0; i < 2; i++){
            int f = tid + i*256;
            int row = f >> 4, c4 = f & 15;
            rb[i] = *(const float4*)(Bg + (k0 + row)*N + c4*4);
        }
    };
    auto sts_tile = [&](int buf){
        #pragma unroll
        for (int i = 0; i < 4; i++){
            int f = tid + i*256;
            int row = f >> 3, c4 = f & 7;
            As[buf][c4*4+0][row] = ra[i].x;
            As[buf][c4*4+1][row] = ra[i].y;
            As[buf][c4*4+2][row] = ra[i].z;
            As[buf][c4*4+3][row] = ra[i].w;
        }
        #pragma unroll
        for (int i = 0; i < 2; i++){
            int f = tid + i*256;
            int row = f >> 4, c4 = f & 15;
            *(float4*)&Bs[buf][row][c4*4] = rb[i];
        }
    };

    ldg_tile(0);
    sts_tile(0);
    __syncthreads();

    const int KT = KK/BK;
    int buf = 0;
    for (int kt = 0; kt < KT; kt++){
        if (kt + 1 < KT) ldg_tile((kt+1)*BK);
        #pragma unroll
        for (int k = 0; k < BK; k++){
            float4 a0 = *(const float4*)&As[buf][k][ty*8];
            float4 a1 = *(const float4*)&As[buf][k][ty*8+4];
            float4 b0 = *(const float4*)&Bs[buf][k][tx*4];
            float a[8] = {a0.x,a0.y,a0.z,a0.w,a1.x,a1.y,a1.z,a1.w};
            float b[4] = {b0.x,b0.y,b0.z,b0.w};
            #pragma unroll
            for (int i = 0; i < 8; i++)
                #pragma unroll
                for (int j = 0; j < 4; j++)
                    acc[i][j] += a[i]*b[j];
        }
        if (kt + 1 < KT){
            sts_tile(buf^1);
            __syncthreads();
            buf ^= 1;
        }
    }

    #pragma unroll
    for (int i = 0; i < 8; i++){
        int gr = bm*BM + ty*8 + i;
        #pragma unroll
        for (int j = 0; j < 4; j++){
            int gc = bn*BN + tx*4 + j;
            C[gr*N + gc] = acc[i][j] + bias[gc];
        }
    }
}

// ============ fp16 mma.sync GEMM, 4-stage cp.async, XOR swizzle =============
#define STG16 8192
#define OFF_BH (4*STG16)          // 32768
#define OFF_SB2 (8*STG16)         // 65536
#define SMEM_MMA (OFF_SB2 + 512)

__global__ void __launch_bounds__(256) gemmMMA_kernel(const float* __restrict__ b2,
                                                      const float* __restrict__ x){
    extern __shared__ char smem[];
    const uint32_t sb = smem_u32(smem);
    float* sbias = (float*)(smem + OFF_SB2);

    const int tid  = threadIdx.x;
    const int lane = tid & 31;
    const int wid  = tid >> 5;
    const int wm   = wid >> 2;
    const int wn   = wid & 3;
    const int bn   = blockIdx.x;        // 0..5
    const int bm   = blockIdx.y;        // 0..729

    if (tid < 128) sbias[tid] = b2[bn*128 + tid];

    const __half* Asrc = g_hiddenH + (size_t)bm*128*HID;
    const __half* Bsrc = g_w2tH    + (size_t)bn*128*HID;

    auto load_stage = [&](int kt, int st){
        uint32_t ab = sb + st*STG16;
        uint32_t bb = sb + OFF_BH + st*STG16;
        #pragma unroll
        for (int i = 0; i < 2; i++){
            int task = tid + i*256;
            int row = task >> 2, q = task & 3;
            uint32_t col = (uint32_t)(q*16) ^ (uint32_t)(((row>>1)&3)<<4);
            cpa16(ab + row*64 + col, Asrc + (size_t)row*HID + kt*32 + q*8);
        }
        #pragma unroll
        for (int i = 0; i < 2; i++){
            int task = tid + i*256;
            int row = task >> 2, q = task & 3;
            uint32_t col = (uint32_t)(q*16) ^ (uint32_t)(((row>>1)&3)<<4);
            cpa16(bb + row*64 + col, Bsrc + (size_t)row*HID + kt*32 + q*8);
        }
        CP_COMMIT();
    };

    float acc[4][4][4];
    #pragma unroll
    for (int i = 0; i < 4; i++)
        #pragma unroll
        for (int j = 0; j < 4; j++)
            #pragma unroll
            for (int k = 0; k < 4; k++) acc[i][j][k] = 0.0f;

    const int arow = lane & 15;
    const uint32_t acb = (lane & 16) ? 16u : 0u;
    const uint32_t aswz = (uint32_t)(((arow>>1)&3)<<4);
    const int brow = (lane & 7) | ((lane & 16) >> 1);
    const uint32_t bcb = (lane & 8) ? 16u : 0u;
    const uint32_t bswz = (uint32_t)(((brow>>1)&3)<<4);
    uint32_t aoff[4], boff[2];
    #pragma unroll
    for (int mi = 0; mi < 4; mi++) aoff[mi] = (uint32_t)((wm*64 + mi*16 + arow)*64);
    #pragma unroll
    for (int p = 0; p < 2; p++)   boff[p]  = (uint32_t)((wn*32 + p*16 + brow)*64);

    load_stage(0, 0); load_stage(1, 1); load_stage(2, 2);

    #pragma unroll 1
    for (int kt = 0; kt < 8; kt++){
        if (kt < 6) cpwait<2>(); else if (kt == 6) cpwait<1>(); else cpwait<0>();
        __syncthreads();
        if (kt + 3 < 8) load_stage(kt+3, (kt+3)&3);

        uint32_t abase = sb + (kt&3)*STG16;
        uint32_t bbase = sb + OFF_BH + (kt&3)*STG16;
        #pragma unroll
        for (int ks = 0; ks < 2; ks++){
            uint32_t acol = (acb + (uint32_t)(ks*32)) ^ aswz;
            uint32_t bcol = (bcb + (uint32_t)(ks*32)) ^ bswz;
            uint32_t aF[4][4];
            uint32_t bF[4][2];
            LDSM_X4(aF[0][0],aF[0][1],aF[0][2],aF[0][3], abase + aoff[0] + acol);
            LDSM_X4(aF[1][0],aF[1][1],aF[1][2],aF[1][3], abase + aoff[1] + acol);
            LDSM_X4(aF[2][0],aF[2][1],aF[2][2],aF[2][3], abase + aoff[2] + acol);
            LDSM_X4(aF[3][0],aF[3][1],aF[3][2],aF[3][3], abase + aoff[3] + acol);
            LDSM_X4(bF[0][0],bF[0][1],bF[1][0],bF[1][1], bbase + boff[0] + bcol);
            LDSM_X4(bF[2][0],bF[2][1],bF[3][0],bF[3][1], bbase + boff[1] + bcol);
            #pragma unroll
            for (int mi = 0; mi < 4; mi++)
                #pragma unroll
                for (int ni = 0; ni < 4; ni++)
                    MMA_F16(acc[mi][ni][0],acc[mi][ni][1],acc[mi][ni][2],acc[mi][ni][3],
                            aF[mi][0],aF[mi][1],aF[mi][2],aF[mi][3],
                            bF[ni][0],bF[ni][1]);
        }
    }

    // ---- fused epilogue: bias + activation -> fp32 Pl/Ev/Vm ----
    const int grp = bn >> 1;
    const int h0  = (bn & 1)*128;
    float* outp = (grp == 0) ? g_Pl : (grp == 1) ? g_Ev : g_Vm;
    const int qr = lane >> 2, qc = (lane & 3)*2;

    #pragma unroll
    for (int mi = 0; mi < 4; mi++){
        int r0 = bm*128 + wm*64 + mi*16 + qr;
        int r1 = r0 + 8;
        float s0 = 0.0f, s1 = 0.0f;
        if (grp == 0){ s0 = g_pfrac[r0]; s1 = g_pfrac[r1]; }
        if (grp == 1){ s0 = x[r0*6 + 1]; s1 = x[r1*6 + 1]; }
        #pragma unroll
        for (int ni = 0; ni < 4; ni++){
            int cl = wn*32 + ni*8 + qc;
            float b0v = sbias[cl], b1v = sbias[cl+1];
            float v0 = acc[mi][ni][0] + b0v;
            float v1 = acc[mi][ni][1] + b1v;
            float v2 = acc[mi][ni][2] + b0v;
            float v3 = acc[mi][ni][3] + b1v;
            float2 o0, o1;
            if (grp == 0){
                o0.x = s0*fminf(fmaxf(v0*(2.0f/6.0f)+0.5f,0.0f),1.0f);
                o0.y = s0*fminf(fmaxf(v1*(2.0f/6.0f)+0.5f,0.0f),1.0f);
                o1.x = s1*fminf(fmaxf(v2*(2.0f/6.0f)+0.5f,0.0f),1.0f);
                o1.y = s1*fminf(fmaxf(v3*(2.0f/6.0f)+0.5f,0.0f),1.0f);
            } else if (grp == 1){
                o0.x = s0*fmaxf(v0,0.0f)*2.0f;
                o0.y = s0*fmaxf(v1,0.0f)*2.0f;
                o1.x = s1*fmaxf(v2,0.0f)*2.0f;
                o1.y = s1*fmaxf(v3,0.0f)*2.0f;
            } else {
                o0.x = expf(v0); o0.y = expf(v1);
                o1.x = expf(v2); o1.y = expf(v3);
            }
            *(float2*)(outp + (size_t)r0*NH + h0 + cl) = o0;
            *(float2*)(outp + (size_t)r1*NH + h0 + cl) = o1;
        }
    }
}

// ---------------- fcW + fcR activations, one launch --------------------------
__global__ void __launch_bounds__(256) actWR_kernel(){
    int h = threadIdx.x;
    if (blockIdx.x < NS){
        int s = blockIdx.x;
        const float* w = g_w + s*(NH*7);
        float kp = sigf(w[h]);
        float ks = sigf(w[NH+h]);
        float kg = sigf(w[2*NH+h])/10.0f;
        float gp = sigf(w[3*NH+h]);
        float e  = expf(w[4*NH+h]);
        float gL = e*e;
        float qb = fmaxf(w[5*NH+h], 0.0f);
        float gar = w[6*NH+h];

        __shared__ float red[8];
        float m = gar;
        #pragma unroll
        for (int o = 16; o; o >>= 1) m = fmaxf(m, __shfl_xor_sync(0xffffffffu, m, o));
        if ((h & 31) == 0) red[h>>5] = m;
        __syncthreads();
        if (h < 32){
            float v = (h < 8) ? red[h] : -1e30f;
            #pragma unroll
            for (int o = 4; o; o >>= 1) v = fmaxf(v, __shfl_xor_sync(0xffffffffu, v, o));
            if (h == 0) red[0] = v;
        }
        __syncthreads();
        float M = red[0];
        __syncthreads();
        float eg = expf(gar - M);
        float sm = eg;
        #pragma unroll
        for (int o = 16; o; o >>= 1) sm += __shfl_xor_sync(0xffffffffu, sm, o);
        if ((h & 31) == 0) red[h>>5] = sm;
        __syncthreads();
        if (h < 32){
            float v = (h < 8) ? red[h] : 0.0f;
            #pragma unroll
            for (int o = 4; o; o >>= 1) v += __shfl_xor_sync(0xffffffffu, v, o);
            if (h == 0) red[0] = v;
        }
        __syncthreads();
        float S = red[0];

        int ix = s*NH + h;
        g_kp[ix] = kp; g_ks[ix] = ks; g_kg[ix] = kg; g_gp[ix] = gp;
        g_gL[ix] = gL; g_qb[ix] = qb; g_ga[ix] = eg/S;
    } else {
        int s = blockIdx.x - NS;
        const float* rf = g_rfraw + s*(NH*NR) + h*NR;
        float v[NR];
        float m = -1e30f;
        #pragma unroll
        for (int j = 0; j < NR; j++){ v[j] = fmaxf(rf[j], 0.0f); m = fmaxf(m, v[j]); }
        float ssum = 0.0f;
        #pragma unroll
        for (int j = 0; j < NR; j++){ v[j] = expf(v[j]-m); ssum += v[j]; }
        float* out = g_r + s*(NH*NR) + h*NR;
        #pragma unroll
        for (int j = 0; j < NR; j++) out[j] = v[j]/ssum;
    }
}

// ==== fused scan + conv: register ring, per-warp partials, no Q round-trip ==
__global__ void __launch_bounds__(256) scanconv_kernel(float* __restrict__ out){
    __shared__ float sPs[368];
    __shared__ float yW[8][368];       // per-warp conv partial sums over t'

    const int s = blockIdx.x, tid = threadIdx.x, h = tid;
    const int w = tid >> 5;

    for (int i = tid; i < NT; i += 256) sPs[i] = g_PsT[s*QSTR + i];

    const int idx0 = (s << 8) + h;
    const float kp = g_kp[idx0], ks = g_ks[idx0], kg = g_kg[idx0];
    const float gp = g_gp[idx0], gL = g_gL[idx0], qb = g_qb[idx0];
    const float gah = g_ga[idx0];
    float c[NR];
    {
        const float* rp = g_r + (size_t)idx0*NR;
        #pragma unroll
        for (int j = 0; j < NR; j++) c[j] = gah*rp[j];
    }
    __syncthreads();

    float Sf = 0.0f, Ss = 0.0f, Sg = 0.0f;
    const size_t str = (size_t)NS*NH;
    float fl[8], fev[8], fm[8];
    {
        size_t ix = idx0;
        #pragma unroll
        for (int i = 0; i < 8; i++){
            fl[i] = g_Pl[ix]; fev[i] = g_Ev[ix]; fm[i] = g_Vm[ix];
            ix += str;
        }
    }
    size_t ixn = (size_t)idx0 + 8*str;

    float q16[16];

    auto step = [&](int tt, float cfl, float cfev, float cfm){
        float fs = sPs[tt];
        float a  = Sf + fs;
        float qf = fminf(a, cfm);
        Sf = fmaxf(a - cfm, 0.0f);
        float H  = fmaxf(Ss + cfl + qf - cfev, 0.0f);
        float qp = fmaxf(kp*(H - gL), 0.0f);
        float qsa = ks*fminf(H, gL);
        Ss = H - qp - qsa;
        float sgin = Sg + qsa*gp;
        float qg = kg*sgin + qb;
        Sg = (1.0f - kg)*sgin - qb;
        return qp + qsa*(1.0f - gp) + qg;
    };

    #pragma unroll 1
    for (int tb = 0; tb < 352; tb += 16){
        #pragma unroll
        for (int i = 0; i < 16; i++){
            int t = tb + i;
            float cfl = fl[i&7], cfev = fev[i&7], cfm = fm[i&7];
            if (t + 8 < NT){
                fl[i&7] = g_Pl[ixn]; fev[i&7] = g_Ev[ixn]; fm[i&7] = g_Vm[ixn];
                ixn += str;
            }
            q16[i] = step(t, cfl, cfev, cfm);
            if (t >= 15){
                float val = 0.0f;
                #pragma unroll
                for (int j = 0; j < 16; j++) val += c[j]*q16[(i+1+j)&15];
                #pragma unroll
                for (int o = 16; o; o >>= 1) val += __shfl_xor_sync(0xffffffffu, val, o);
                if ((tid & 31) == 0) yW[w][t-15] = val;
            }
        }
    }
    // tail: t = 352..364, slot = i (352 % 16 == 0)
    #pragma unroll
    for (int i = 0; i < 13; i++){
        int t = 352 + i;
        float cfl = fl[i&7], cfev = fev[i&7], cfm = fm[i&7];
        if (t + 8 < NT){
            fl[i&7] = g_Pl[ixn]; fev[i&7] = g_Ev[ixn]; fm[i&7] = g_Vm[ixn];
            ixn += str;
        }
        q16[i] = step(t, cfl, cfev, cfm);
        float val = 0.0f;
        #pragma unroll
        for (int j = 0; j < 16; j++) val += c[j]*q16[(i+1+j)&15];
        #pragma unroll
        for (int o = 16; o; o >>= 1) val += __shfl_xor_sync(0xffffffffu, val, o);
        if ((tid & 31) == 0) yW[w][t-15] = val;
    }
    __syncthreads();

    for (int t = tid; t < TOUT; t += 256){
        float acc = 0.0f;
        #pragma unroll
        for (int w2 = 0; w2 < 8; w2++) acc += yW[w2][t];
        out[t*NS + s] = acc;
    }
}

// ---------------- launch ----------------------------------------------------
extern "C" void kernel_launch(void* const* d_in, const int* in_sizes, int n_in,
                              void* d_out, int out_size){
    const float* x      = (const float*)d_in[0];
    const float* xc     = (const float*)d_in[1];
    const float* fcW_w1 = (const float*)d_in[2];
    const float* fcW_b1 = (const float*)d_in[3];
    const float* fcW_w2 = (const float*)d_in[4];
    const float* fcW_b2 = (const float*)d_in[5];
    const float* fcT_w1 = (const float*)d_in[6];
    const float* fcT_b1 = (const float*)d_in[7];
    const float* fcT_w2 = (const float*)d_in[8];
    const float* fcT_b2 = (const float*)d_in[9];
    const float* fcR_w1 = (const float*)d_in[10];
    const float* fcR_b1 = (const float*)d_in[11];
    const float* fcR_w2 = (const float*)d_in[12];
    const float* fcR_b2 = (const float*)d_in[13];
    float* out = (float*)d_out;

    cudaFuncSetAttribute(gemmMMA_kernel, cudaFuncAttributeMaxDynamicSharedMemorySize, SMEM_MMA);

    // NOTE: gemmMMA is the 4th launch -> captured by the profiler next round.
    setup_kernel<<<365+192+768, 256>>>(x, xc, fcT_w2, fcW_w1, fcW_b1, fcR_w1, fcR_b1, fcT_w1, fcT_b1);
    gemmWR_kernel<<<dim3(92, 2), 256>>>(fcW_w2, fcW_b2, fcR_w2, fcR_b2);
    hiddenT_kernel<<<dim3(NS, 4), 128>>>(x, fcT_w1);
    gemmMMA_kernel<<<dim3(6, MTILES), 256, SMEM_MMA>>>(fcT_b2, x);
    actWR_kernel<<<2*NS, 256>>>();
    scanconv_kernel<<<NS, 256>>>(out);
}

// round 9
// speedup vs baseline: 1.5648x; 1.0292x over previous
#include <cuda_runtime.h>
#include <cuda_fp16.h>
#include <cstdint>
#include <math.h>

#define NT  365
#define NS  256
#define NH  256
#define NG  32
#define NR  16
#define HID 256
#define NTS (NT*NS)          // 93440
#define TOUT (NT-NR+1)       // 350
#define MTILES 730           // 93440/128
#define QSTR 372             // padded time stride for PsT
#define TCHUNK 92            // hiddenT t-chunk (4*92=368 >= 365)

// ---------------- scratch (device globals) ----------------------------------
__device__ __half g_hiddenH[NTS*HID]; // fcT layer-1 output (tanh, fp16)
__device__ float g_Pl[NTS*NH];
__device__ float g_Ev[NTS*NH];
__device__ float g_Vm[NTS*NH];
__device__ float g_hidW[NS*HID];
__device__ float g_hidR[NS*HID];
__device__ float g_baseT[NS*HID];
__device__ float g_w[NS*NH*7];
__device__ float g_rfraw[NS*NH*NR];
__device__ float g_kp[NS*NH], g_ks[NS*NH], g_kg[NS*NH], g_gp[NS*NH];
__device__ float g_gL[NS*NH], g_qb[NS*NH], g_ga[NS*NH];
__device__ float g_r[NS*NH*NR];
__device__ float g_PsT[NS*QSTR];      // snowfall, transposed [s][t]
__device__ float g_pfrac[NTS];
__device__ __half g_w2tH[768*HID];    // fcT_w2^T, fp16

__device__ __forceinline__ float sigf(float x){ return 1.0f/(1.0f+expf(-x)); }
__device__ __forceinline__ float tanha(float x){
    float y; asm("tanh.approx.f32 %0, %1;" : "=f"(y) : "f"(x)); return y;
}

__device__ __forceinline__ uint32_t smem_u32(const void* p){
    uint32_t a;
    asm("{ .reg .u64 t; cvta.to.shared.u64 t, %1; cvt.u32.u64 %0, t; }" : "=r"(a) : "l"(p));
    return a;
}
__device__ __forceinline__ void cpa16(uint32_t dst, const void* src){
    asm volatile("cp.async.cg.shared.global [%0], [%1], 16;" :: "r"(dst), "l"(src) : "memory");
}
#define CP_COMMIT() asm volatile("cp.async.commit_group;" ::: "memory")
template<int N> __device__ __forceinline__ void cpwait(){
    asm volatile("cp.async.wait_group %0;" :: "n"(N) : "memory");
}
#define LDSM_X4(r0,r1,r2,r3,addr) \
    asm volatile("ldmatrix.sync.aligned.m8n8.x4.shared.b16 {%0,%1,%2,%3}, [%4];" \
        : "=r"(r0),"=r"(r1),"=r"(r2),"=r"(r3) : "r"(addr))
#define MMA_F16(c0,c1,c2,c3,a0,a1,a2,a3,b0,b1) \
    asm volatile("mma.sync.aligned.m16n8k16.row.col.f32.f16.f16.f32 " \
        "{%0,%1,%2,%3}, {%4,%5,%6,%7}, {%8,%9}, {%0,%1,%2,%3};" \
        : "+f"(c0),"+f"(c1),"+f"(c2),"+f"(c3) \
        : "r"(a0),"r"(a1),"r"(a2),"r"(a3), "r"(b0),"r"(b1))

// ============ setup: prep + transposeB(fp16) + layer1 in one launch =========
__global__ void __launch_bounds__(256) setup_kernel(
        const float* __restrict__ x, const float* __restrict__ xc,
        const float* __restrict__ w2,
        const float* __restrict__ wW1, const float* __restrict__ bW1,
        const float* __restrict__ wR1, const float* __restrict__ bR1,
        const float* __restrict__ wT1, const float* __restrict__ bT1){
    __shared__ float sh[32*33];
    int bid = blockIdx.x, tid = threadIdx.x;
    if (bid < 365){
        int i = bid*256 + tid;
        float P  = x[i*6+0];
        float T1 = x[i*6+2];
        float T2 = x[i*6+3];
        float ratio = (T1+T2)/(T2-T1);
        ratio = fminf(fmaxf(ratio,-1.0f),1.0f);
        float vf = acosf(ratio)/3.1415f;
        if (T1 >= 0.0f) vf = 0.0f;
        if (T2 <= 0.0f) vf = 1.0f;
        int s = i & 255, t = i >> 8;
        g_PsT[s*QSTR + t] = P*vf;
        g_pfrac[i] = P*(1.0f-vf);
    } else if (bid < 365+192){
        int tb = bid - 365;
        int nb = (tb % 24)*32, kb = (tb / 24)*32;
        int tx = tid & 31, ty = tid >> 5;
        #pragma unroll
        for (int r = 0; r < 32; r += 8)
            sh[(ty+r)*33 + tx] = w2[(kb+ty+r)*768 + nb + tx];
        __syncthreads();
        #pragma unroll
        for (int r = 0; r < 32; r += 8)
            g_w2tH[(nb+ty+r)*HID + kb + tx] = __float2half(sh[tx*33 + ty + r]);
    } else {
        int lb = bid - 557;
        int s = lb & 255, mode = lb >> 8, h = tid;
        float* xs = sh;
        if (h < NG) xs[h] = xc[s*NG + h];
        __syncthreads();
        const float* w; const float* b; float* out; bool dotanh;
        if (mode == 0){ w = wW1;      b = bW1; out = g_hidW;  dotanh = true;  }
        else if (mode == 1){ w = wR1; b = bR1; out = g_hidR;  dotanh = true;  }
        else { w = wT1 + 6*HID;       b = bT1; out = g_baseT; dotanh = false; }
        float acc = b[h];
        #pragma unroll
        for (int g = 0; g < NG; g++) acc += xs[g]*w[g*HID + h];
        out[s*HID + h] = dotanh ? tanhf(acc) : acc;
    }
}

// ---------------- fcT layer-1: block per (s, t-chunk), regs-resident weights -
__global__ void __launch_bounds__(128) hiddenT_kernel(const float* __restrict__ x,
                                                      const float* __restrict__ wT1){
    const int s = blockIdx.x;
    const int t0 = blockIdx.y*TCHUNK;
    const int t1 = min(t0 + TCHUNK, NT);
    const int nt = t1 - t0;
    const int hl = threadIdx.x, hh = hl*2;

    float w0[6], w1[6];
    #pragma unroll
    for (int i = 0; i < 6; i++){
        w0[i] = wT1[i*HID + hh];
        w1[i] = wT1[i*HID + hh + 1];
    }
    const float b0 = g_baseT[s*HID + hh];
    const float b1 = g_baseT[s*HID + hh + 1];

    __shared__ float sx[TCHUNK*6];
    for (int u = hl; u < nt*6; u += 128){
        int j = u/6, i = u - j*6;
        sx[u] = x[(size_t)(t0 + j)*(NS*6) + s*6 + i];
    }
    __syncthreads();

    __half* dst = g_hiddenH + ((size_t)(t0*NS + s))*HID + hh;
    #pragma unroll 4
    for (int j = 0; j < nt; j++){
        const float* xv = sx + j*6;
        float a0 = b0, a1 = b1;
        #pragma unroll
        for (int i = 0; i < 6; i++){
            float f = xv[i];
            a0 += f*w0[i];
            a1 += f*w1[i];
        }
        *(half2*)(dst + (size_t)j*(NS*HID)) = __floats2half2_rn(tanha(a0), tanha(a1));
    }
}

// ---------------- combined small SIMT GEMMs (fcW + fcR layer 2) -------------
#define BM 128
#define BN 64
#define BK 32
#define KK 256

__global__ void __launch_bounds__(256) gemmWR_kernel(
        const float* __restrict__ Wb, const float* __restrict__ Wbias,
        const float* __restrict__ Rb, const float* __restrict__ Rbias){
    const float* A; float* C; const float* B; const float* bias; int N; int bn;
    if (blockIdx.x < 28){ A = g_hidW; C = g_w;     B = Wb; bias = Wbias; N = NH*7;  bn = blockIdx.x; }
    else                { A = g_hidR; C = g_rfraw; B = Rb; bias = Rbias; N = NH*NR; bn = blockIdx.x - 28; }

    __shared__ float As[2][BK][BM];
    __shared__ float Bs[2][BK][BN];

    const int tid = threadIdx.x;
    const int tx  = tid & 15;
    const int ty  = tid >> 4;
    const int bm  = blockIdx.y;

    const float* Ag = A + bm*BM*KK;
    const float* Bg = B + bn*BN;

    float acc[8][4];
    #pragma unroll
    for (int i = 0; i < 8; i++)
        #pragma unroll
        for (int j = 0; j < 4; j++) acc[i][j] = 0.0f;

    float4 ra[4], rb[2];
    auto ldg_tile = [&](int k0){
        #pragma unroll
        for (int i = 0; i < 4; i++){
            int f = tid + i*256;
            int row = f >> 3, c4 = f & 7;
            ra[i] = *(const float4*)(Ag + row*KK + k0 + c4*4);
        }
        #pragma unroll
        for (int i = 0; i < 2; i++){
            int f = tid + i*256;
            int row = f >> 4, c4 = f & 15;
            rb[i] = *(const float4*)(Bg + (k0 + row)*N + c4*4);
        }
    };
    auto sts_tile = [&](int buf){
        #pragma unroll
        for (int i = 0; i < 4; i++){
            int f = tid + i*256;
            int row = f >> 3, c4 = f & 7;
            As[buf][c4*4+0][row] = ra[i].x;
            As[buf][c4*4+1][row] = ra[i].y;
            As[buf][c4*4+2][row] = ra[i].z;
            As[buf][c4*4+3][row] = ra[i].w;
        }
        #pragma unroll
        for (int i = 0; i < 2; i++){
            int f = tid + i*256;
            int row = f >> 4, c4 = f & 15;
            *(float4*)&Bs[buf][row][c4*4] = rb[i];
        }
    };

    ldg_tile(0);
    sts_tile(0);
    __syncthreads();

    const int KT = KK/BK;
    int buf = 0;
    for (int kt = 0; kt < KT; kt++){
        if (kt + 1 < KT) ldg_tile((kt+1)*BK);
        #pragma unroll
        for (int k = 0; k < BK; k++){
            float4 a0 = *(const float4*)&As[buf][k][ty*8];
            float4 a1 = *(const float4*)&As[buf][k][ty*8+4];
            float4 b0 = *(const float4*)&Bs[buf][k][tx*4];
            float a[8] = {a0.x,a0.y,a0.z,a0.w,a1.x,a1.y,a1.z,a1.w};
            float b[4] = {b0.x,b0.y,b0.z,b0.w};
            #pragma unroll
            for (int i = 0; i < 8; i++)
                #pragma unroll
                for (int j = 0; j < 4; j++)
                    acc[i][j] += a[i]*b[j];
        }
        if (kt + 1 < KT){
            sts_tile(buf^1);
            __syncthreads();
            buf ^= 1;
        }
    }

    #pragma unroll
    for (int i = 0; i < 8; i++){
        int gr = bm*BM + ty*8 + i;
        #pragma unroll
        for (int j = 0; j < 4; j++){
            int gc = bn*BN + tx*4 + j;
            C[gr*N + gc] = acc[i][j] + bias[gc];
        }
    }
}

// ====== fp16 mma.sync GEMM, A-stationary: 1 CTA per 128-row tile ============
// A tile (128x256 fp16 = 64KB) resident in smem; loop bn=0..5, stream B in a
// 4-stage 8KB ring. 2 CTAs/SM.
#define OFF_BB 65536
#define OFF_SBIAS (OFF_BB + 4*8192)     // 98304
#define SMEM_MMA (OFF_SBIAS + 3072)     // 101376

__global__ void __launch_bounds__(256,2) gemmMMA_kernel(const float* __restrict__ b2,
                                                        const float* __restrict__ x){
    extern __shared__ char smem[];
    const uint32_t sb = smem_u32(smem);
    float* sbias = (float*)(smem + OFF_SBIAS);

    const int tid  = threadIdx.x;
    const int lane = tid & 31;
    const int wid  = tid >> 5;
    const int wm   = wid >> 2;
    const int wn   = wid & 3;
    const int bm   = blockIdx.x;        // 0..729

    #pragma unroll
    for (int i = 0; i < 3; i++) sbias[tid + i*256] = b2[tid + i*256];

    const __half* Asrc = g_hiddenH + (size_t)bm*128*HID;

    // ---- load full A tile: 8 chunks x 8KB ----
    {
        #pragma unroll
        for (int c = 0; c < 8; c++){
            #pragma unroll
            for (int i = 0; i < 2; i++){
                int task = tid + i*256;
                int row = task >> 2, q = task & 3;
                uint32_t col = (uint32_t)(q*16) ^ (uint32_t)(((row>>1)&3)<<4);
                cpa16(sb + c*8192 + row*64 + col, Asrc + (size_t)row*HID + c*32 + q*8);
            }
        }
    }
    auto loadB = [&](int g){
        int bnn = g >> 3, kt = g & 7, st = g & 3;
        const __half* Bsrc = g_w2tH + (size_t)bnn*128*HID;
        #pragma unroll
        for (int i = 0; i < 2; i++){
            int task = tid + i*256;
            int row = task >> 2, q = task & 3;
            uint32_t col = (uint32_t)(q*16) ^ (uint32_t)(((row>>1)&3)<<4);
            cpa16(sb + OFF_BB + st*8192 + row*64 + col, Bsrc + (size_t)row*HID + kt*32 + q*8);
        }
    };
    loadB(0); CP_COMMIT();          // group: A + B0
    loadB(1); CP_COMMIT();          // group: B1
    loadB(2); CP_COMMIT();          // group: B2

    // ldmatrix lane mappings
    const int arow = lane & 15;
    const uint32_t acb = (lane & 16) ? 16u : 0u;
    const uint32_t aswz = (uint32_t)(((arow>>1)&3)<<4);
    const int brow = (lane & 7) | ((lane & 16) >> 1);
    const uint32_t bcb = (lane & 8) ? 16u : 0u;
    const uint32_t bswz = (uint32_t)(((brow>>1)&3)<<4);
    uint32_t aoff[4], boff[2];
    #pragma unroll
    for (int mi = 0; mi < 4; mi++) aoff[mi] = (uint32_t)((wm*64 + mi*16 + arow)*64);
    #pragma unroll
    for (int p = 0; p < 2; p++)   boff[p]  = (uint32_t)((wn*32 + p*16 + brow)*64);

    const int qr = lane >> 2, qc = (lane & 3)*2;

    float acc[4][4][4];
    #pragma unroll
    for (int i = 0; i < 4; i++)
        #pragma unroll
        for (int j = 0; j < 4; j++)
            #pragma unroll
            for (int k = 0; k < 4; k++) acc[i][j][k] = 0.0f;

    #pragma unroll 1
    for (int g = 0; g < 48; g++){
        if (g >= 1 && g + 2 < 48){ loadB(g+2); CP_COMMIT(); }
        if (g + 2 < 48) cpwait<2>(); else if (g + 1 < 48) cpwait<1>(); else cpwait<0>();
        __syncthreads();

        const int kt = g & 7, st = g & 3;
        uint32_t abase = sb + kt*8192;
        uint32_t bbase = sb + OFF_BB + st*8192;
        #pragma unroll
        for (int ks = 0; ks < 2; ks++){
            uint32_t acol = (acb + (uint32_t)(ks*32)) ^ aswz;
            uint32_t bcol = (bcb + (uint32_t)(ks*32)) ^ bswz;
            uint32_t aF[4][4];
            uint32_t bF[4][2];
            LDSM_X4(aF[0][0],aF[0][1],aF[0][2],aF[0][3], abase + aoff[0] + acol);
            LDSM_X4(aF[1][0],aF[1][1],aF[1][2],aF[1][3], abase + aoff[1] + acol);
            LDSM_X4(aF[2][0],aF[2][1],aF[2][2],aF[2][3], abase + aoff[2] + acol);
            LDSM_X4(aF[3][0],aF[3][1],aF[3][2],aF[3][3], abase + aoff[3] + acol);
            LDSM_X4(bF[0][0],bF[0][1],bF[1][0],bF[1][1], bbase + boff[0] + bcol);
            LDSM_X4(bF[2][0],bF[2][1],bF[3][0],bF[3][1], bbase + boff[1] + bcol);
            #pragma unroll
            for (int mi = 0; mi < 4; mi++)
                #pragma unroll
                for (int ni = 0; ni < 4; ni++)
                    MMA_F16(acc[mi][ni][0],acc[mi][ni][1],acc[mi][ni][2],acc[mi][ni][3],
                            aF[mi][0],aF[mi][1],aF[mi][2],aF[mi][3],
                            bF[ni][0],bF[ni][1]);
        }

        if (kt == 7){
            // ---- fused epilogue for this bn: bias + activation -> Pl/Ev/Vm ----
            const int bnn = g >> 3;
            const int grp = bnn >> 1;
            const int h0  = (bnn & 1)*128;
            float* outp = (grp == 0) ? g_Pl : (grp == 1) ? g_Ev : g_Vm;
            #pragma unroll
            for (int mi = 0; mi < 4; mi++){
                int r0 = bm*128 + wm*64 + mi*16 + qr;
                int r1 = r0 + 8;
                float s0 = 0.0f, s1 = 0.0f;
                if (grp == 0){ s0 = g_pfrac[r0]; s1 = g_pfrac[r1]; }
                if (grp == 1){ s0 = x[r0*6 + 1]; s1 = x[r1*6 + 1]; }
                #pragma unroll
                for (int ni = 0; ni < 4; ni++){
                    int cl = wn*32 + ni*8 + qc;
                    float b0v = sbias[bnn*128 + cl], b1v = sbias[bnn*128 + cl + 1];
                    float v0 = acc[mi][ni][0] + b0v;
                    float v1 = acc[mi][ni][1] + b1v;
                    float v2 = acc[mi][ni][2] + b0v;
                    float v3 = acc[mi][ni][3] + b1v;
                    float2 o0, o1;
                    if (grp == 0){
                        o0.x = s0*fminf(fmaxf(v0*(2.0f/6.0f)+0.5f,0.0f),1.0f);
                        o0.y = s0*fminf(fmaxf(v1*(2.0f/6.0f)+0.5f,0.0f),1.0f);
                        o1.x = s1*fminf(fmaxf(v2*(2.0f/6.0f)+0.5f,0.0f),1.0f);
                        o1.y = s1*fminf(fmaxf(v3*(2.0f/6.0f)+0.5f,0.0f),1.0f);
                    } else if (grp == 1){
                        o0.x = s0*fmaxf(v0,0.0f)*2.0f;
                        o0.y = s0*fmaxf(v1,0.0f)*2.0f;
                        o1.x = s1*fmaxf(v2,0.0f)*2.0f;
                        o1.y = s1*fmaxf(v3,0.0f)*2.0f;
                    } else {
                        o0.x = expf(v0); o0.y = expf(v1);
                        o1.x = expf(v2); o1.y = expf(v3);
                    }
                    *(float2*)(outp + (size_t)r0*NH + h0 + cl) = o0;
                    *(float2*)(outp + (size_t)r1*NH + h0 + cl) = o1;
                    acc[mi][ni][0] = 0.0f; acc[mi][ni][1] = 0.0f;
                    acc[mi][ni][2] = 0.0f; acc[mi][ni][3] = 0.0f;
                }
            }
        }
    }
}

// ---------------- fcW + fcR activations, one launch --------------------------
__global__ void __launch_bounds__(256) actWR_kernel(){
    int h = threadIdx.x;
    if (blockIdx.x < NS){
        int s = blockIdx.x;
        const float* w = g_w + s*(NH*7);
        float kp = sigf(w[h]);
        float ks = sigf(w[NH+h]);
        float kg = sigf(w[2*NH+h])/10.0f;
        float gp = sigf(w[3*NH+h]);
        float e  = expf(w[4*NH+h]);
        float gL = e*e;
        float qb = fmaxf(w[5*NH+h], 0.0f);
        float gar = w[6*NH+h];

        __shared__ float red[8];
        float m = gar;
        #pragma unroll
        for (int o = 16; o; o >>= 1) m = fmaxf(m, __shfl_xor_sync(0xffffffffu, m, o));
        if ((h & 31) == 0) red[h>>5] = m;
        __syncthreads();
        if (h < 32){
            float v = (h < 8) ? red[h] : -1e30f;
            #pragma unroll
            for (int o = 4; o; o >>= 1) v = fmaxf(v, __shfl_xor_sync(0xffffffffu, v, o));
            if (h == 0) red[0] = v;
        }
        __syncthreads();
        float M = red[0];
        __syncthreads();
        float eg = expf(gar - M);
        float sm = eg;
        #pragma unroll
        for (int o = 16; o; o >>= 1) sm += __shfl_xor_sync(0xffffffffu, sm, o);
        if ((h & 31) == 0) red[h>>5] = sm;
        __syncthreads();
        if (h < 32){
            float v = (h < 8) ? red[h] : 0.0f;
            #pragma unroll
            for (int o = 4; o; o >>= 1) v += __shfl_xor_sync(0xffffffffu, v, o);
            if (h == 0) red[0] = v;
        }
        __syncthreads();
        float S = red[0];

        int ix = s*NH + h;
        g_kp[ix] = kp; g_ks[ix] = ks; g_kg[ix] = kg; g_gp[ix] = gp;
        g_gL[ix] = gL; g_qb[ix] = qb; g_ga[ix] = eg/S;
    } else {
        int s = blockIdx.x - NS;
        const float* rf = g_rfraw + s*(NH*NR) + h*NR;
        float v[NR];
        float m = -1e30f;
        #pragma unroll
        for (int j = 0; j < NR; j++){ v[j] = fmaxf(rf[j], 0.0f); m = fmaxf(m, v[j]); }
        float ssum = 0.0f;
        #pragma unroll
        for (int j = 0; j < NR; j++){ v[j] = expf(v[j]-m); ssum += v[j]; }
        float* out = g_r + s*(NH*NR) + h*NR;
        #pragma unroll
        for (int j = 0; j < NR; j++) out[j] = v[j]/ssum;
    }
}

// ==== fused scan + conv: register ring, per-warp partials, no Q round-trip ==
__global__ void __launch_bounds__(256) scanconv_kernel(float* __restrict__ out){
    __shared__ float sPs[368];
    __shared__ float yW[8][368];       // per-warp conv partial sums over t'

    const int s = blockIdx.x, tid = threadIdx.x, h = tid;
    const int w = tid >> 5;

    for (int i = tid; i < NT; i += 256) sPs[i] = g_PsT[s*QSTR + i];

    const int idx0 = (s << 8) + h;
    const float kp = g_kp[idx0], ks = g_ks[idx0], kg = g_kg[idx0];
    const float gp = g_gp[idx0], gL = g_gL[idx0], qb = g_qb[idx0];
    const float gah = g_ga[idx0];
    float c[NR];
    {
        const float* rp = g_r + (size_t)idx0*NR;
        #pragma unroll
        for (int j = 0; j < NR; j++) c[j] = gah*rp[j];
    }
    __syncthreads();

    float Sf = 0.0f, Ss = 0.0f, Sg = 0.0f;
    const size_t str = (size_t)NS*NH;
    float fl[8], fev[8], fm[8];
    {
        size_t ix = idx0;
        #pragma unroll
        for (int i = 0; i < 8; i++){
            fl[i] = g_Pl[ix]; fev[i] = g_Ev[ix]; fm[i] = g_Vm[ix];
            ix += str;
        }
    }
    size_t ixn = (size_t)idx0 + 8*str;

    float q16[16];

    auto step = [&](int tt, float cfl, float cfev, float cfm){
        float fs = sPs[tt];
        float a  = Sf + fs;
        float qf = fminf(a, cfm);
        Sf = fmaxf(a - cfm, 0.0f);
        float H  = fmaxf(Ss + cfl + qf - cfev, 0.0f);
        float qp = fmaxf(kp*(H - gL), 0.0f);
        float qsa = ks*fminf(H, gL);
        Ss = H - qp - qsa;
        float sgin = Sg + qsa*gp;
        float qg = kg*sgin + qb;
        Sg = (1.0f - kg)*sgin - qb;
        return qp + qsa*(1.0f - gp) + qg;
    };

    #pragma unroll 1
    for (int tb = 0; tb < 352; tb += 16){
        #pragma unroll
        for (int i = 0; i < 16; i++){
            int t = tb + i;
            float cfl = fl[i&7], cfev = fev[i&7], cfm = fm[i&7];
            if (t + 8 < NT){
                fl[i&7] = g_Pl[ixn]; fev[i&7] = g_Ev[ixn]; fm[i&7] = g_Vm[ixn];
                ixn += str;
            }
            q16[i] = step(t, cfl, cfev, cfm);
            if (t >= 15){
                float val = 0.0f;
                #pragma unroll
                for (int j = 0; j < 16; j++) val += c[j]*q16[(i+1+j)&15];
                #pragma unroll
                for (int o = 16; o; o >>= 1) val += __shfl_xor_sync(0xffffffffu, val, o);
                if ((tid & 31) == 0) yW[w][t-15] = val;
            }
        }
    }
    // tail: t = 352..364
    #pragma unroll
    for (int i = 0; i < 13; i++){
        int t = 352 + i;
        float cfl = fl[i&7], cfev = fev[i&7], cfm = fm[i&7];
        if (t + 8 < NT){
            fl[i&7] = g_Pl[ixn]; fev[i&7] = g_Ev[ixn]; fm[i&7] = g_Vm[ixn];
            ixn += str;
        }
        q16[i] = step(t, cfl, cfev, cfm);
        float val = 0.0f;
        #pragma unroll
        for (int j = 0; j < 16; j++) val += c[j]*q16[(i+1+j)&15];
        #pragma unroll
        for (int o = 16; o; o >>= 1) val += __shfl_xor_sync(0xffffffffu, val, o);
        if ((tid & 31) == 0) yW[w][t-15] = val;
    }
    __syncthreads();

    for (int t = tid; t < TOUT; t += 256){
        float acc = 0.0f;
        #pragma unroll
        for (int w2 = 0; w2 < 8; w2++) acc += yW[w2][t];
        out[t*NS + s] = acc;
    }
}

// ---------------- launch ----------------------------------------------------
extern "C" void kernel_launch(void* const* d_in, const int* in_sizes, int n_in,
                              void* d_out, int out_size){
    const float* x      = (const float*)d_in[0];
    const float* xc     = (const float*)d_in[1];
    const float* fcW_w1 = (const float*)d_in[2];
    const float* fcW_b1 = (const float*)d_in[3];
    const float* fcW_w2 = (const float*)d_in[4];
    const float* fcW_b2 = (const float*)d_in[5];
    const float* fcT_w1 = (const float*)d_in[6];
    const float* fcT_b1 = (const float*)d_in[7];
    const float* fcT_w2 = (const float*)d_in[8];
    const float* fcT_b2 = (const float*)d_in[9];
    const float* fcR_w1 = (const float*)d_in[10];
    const float* fcR_b1 = (const float*)d_in[11];
    const float* fcR_w2 = (const float*)d_in[12];
    const float* fcR_b2 = (const float*)d_in[13];
    float* out = (float*)d_out;

    cudaFuncSetAttribute(gemmMMA_kernel, cudaFuncAttributeMaxDynamicSharedMemorySize, SMEM_MMA);

    setup_kernel<<<365+192+768, 256>>>(x, xc, fcT_w2, fcW_w1, fcW_b1, fcR_w1, fcR_b1, fcT_w1, fcT_b1);
    gemmWR_kernel<<<dim3(92, 2), 256>>>(fcW_w2, fcW_b2, fcR_w2, fcR_b2);
    hiddenT_kernel<<<dim3(NS, 4), 128>>>(x, fcT_w1);
    gemmMMA_kernel<<<MTILES, 256, SMEM_MMA>>>(fcT_b2, x);
    actWR_kernel<<<2*NS, 256>>>();
    scanconv_kernel<<<NS, 256>>>(out);
}

// round 10
// speedup vs baseline: 1.7630x; 1.1266x over previous
#include <cuda_runtime.h>
#include <cuda_fp16.h>
#include <cstdint>
#include <math.h>

#define NT  365
#define NS  256
#define NH  256
#define NG  32
#define NR  16
#define HID 256
#define NTS (NT*NS)          // 93440
#define TOUT (NT-NR+1)       // 350
#define MTILES 730           // 93440/128
#define QSTR 372             // padded time stride for PsT
#define TCHUNK 92            // hiddenT t-chunk (4*92=368 >= 365)

// ---------------- scratch (device globals) ----------------------------------
__device__ __half g_hiddenH[NTS*HID];   // fcT layer-1 output (tanh, fp16)
__device__ uint32_t g_PlEvH[NTS*NH];    // packed half2 {Pl, Ev} per (t,s,h)
__device__ __half g_VmH[NTS*NH];        // Vm fp16
__device__ float g_hidW[NS*HID];
__device__ float g_hidR[NS*HID];
__device__ float g_baseT[NS*HID];
__device__ float g_w[NS*NH*7];
__device__ float g_rfraw[NS*NH*NR];
__device__ float g_kp[NS*NH], g_ks[NS*NH], g_kg[NS*NH], g_gp[NS*NH];
__device__ float g_gL[NS*NH], g_qb[NS*NH], g_ga[NS*NH];
__device__ float g_r[NS*NH*NR];
__device__ float g_PsT[NS*QSTR];        // snowfall, transposed [s][t]
__device__ float g_pfrac[NTS];
__device__ __half g_w2tH[768*HID];      // fcT_w2^T, fp16, COLUMN-PERMUTED
__device__ float g_biasP[768];          // fcT_b2, same permutation

__device__ __forceinline__ float sigf(float x){ return 1.0f/(1.0f+expf(-x)); }
__device__ __forceinline__ float tanha(float x){
    float y; asm("tanh.approx.f32 %0, %1;" : "=f"(y) : "f"(x)); return y;
}

// column permutation for the big GEMM's B matrix (see epilogue packing)
__device__ __forceinline__ int perm_srccol(int colp){
    int tile = colp >> 7, c = colp & 127;
    int wn = c >> 5, ni = (c >> 3) & 3, q = (c >> 1) & 3, comp = c & 1;
    if (tile < 4){
        int h = tile*64 + wn*16 + q*4 + ni;
        return comp*256 + h;            // comp0 -> Pl(seg0), comp1 -> Ev(seg1)
    } else {
        int h = (tile-4)*128 + wn*32 + q*8 + ni*2 + comp;
        return 512 + h;                 // Vm(seg2)
    }
}

__device__ __forceinline__ uint32_t smem_u32(const void* p){
    uint32_t a;
    asm("{ .reg .u64 t; cvta.to.shared.u64 t, %1; cvt.u32.u64 %0, t; }" : "=r"(a) : "l"(p));
    return a;
}
__device__ __forceinline__ void cpa16(uint32_t dst, const void* src){
    asm volatile("cp.async.cg.shared.global [%0], [%1], 16;" :: "r"(dst), "l"(src) : "memory");
}
#define CP_COMMIT() asm volatile("cp.async.commit_group;" ::: "memory")
template<int N> __device__ __forceinline__ void cpwait(){
    asm volatile("cp.async.wait_group %0;" :: "n"(N) : "memory");
}
#define LDSM_X4(r0,r1,r2,r3,addr) \
    asm volatile("ldmatrix.sync.aligned.m8n8.x4.shared.b16 {%0,%1,%2,%3}, [%4];" \
        : "=r"(r0),"=r"(r1),"=r"(r2),"=r"(r3) : "r"(addr))
#define MMA_F16(c0,c1,c2,c3,a0,a1,a2,a3,b0,b1) \
    asm volatile("mma.sync.aligned.m16n8k16.row.col.f32.f16.f16.f32 " \
        "{%0,%1,%2,%3}, {%4,%5,%6,%7}, {%8,%9}, {%0,%1,%2,%3};" \
        : "+f"(c0),"+f"(c1),"+f"(c2),"+f"(c3) \
        : "r"(a0),"r"(a1),"r"(a2),"r"(a3), "r"(b0),"r"(b1))

// ============ setup: prep + permuted transposeB(fp16) + layer1 ==============
__global__ void __launch_bounds__(256) setup_kernel(
        const float* __restrict__ x, const float* __restrict__ xc,
        const float* __restrict__ w2, const float* __restrict__ b2,
        const float* __restrict__ wW1, const float* __restrict__ bW1,
        const float* __restrict__ wR1, const float* __restrict__ bR1,
        const float* __restrict__ wT1, const float* __restrict__ bT1){
    __shared__ float sh[32*33];
    int bid = blockIdx.x, tid = threadIdx.x;
    if (bid < 365){
        int i = bid*256 + tid;
        float P  = x[i*6+0];
        float T1 = x[i*6+2];
        float T2 = x[i*6+3];
        float ratio = (T1+T2)/(T2-T1);
        ratio = fminf(fmaxf(ratio,-1.0f),1.0f);
        float vf = acosf(ratio)/3.1415f;
        if (T1 >= 0.0f) vf = 0.0f;
        if (T2 <= 0.0f) vf = 1.0f;
        int s = i & 255, t = i >> 8;
        g_PsT[s*QSTR + t] = P*vf;
        g_pfrac[i] = P*(1.0f-vf);
    } else if (bid < 365+192){
        int tb = bid - 365;
        int nb = (tb % 24)*32, kb = (tb / 24)*32;
        int tx = tid & 31, ty = tid >> 5;
        int src = perm_srccol(nb + tx);
        #pragma unroll
        for (int r = 0; r < 32; r += 8)
            sh[(ty+r)*33 + tx] = w2[(kb+ty+r)*768 + src];
        __syncthreads();
        #pragma unroll
        for (int r = 0; r < 32; r += 8)
            g_w2tH[(nb+ty+r)*HID + kb + tx] = __float2half(sh[tx*33 + ty + r]);
        if (kb == 0 && ty == 0) g_biasP[nb + tx] = b2[src];
    } else {
        int lb = bid - 557;
        int s = lb & 255, mode = lb >> 8, h = tid;
        float* xs = sh;
        if (h < NG) xs[h] = xc[s*NG + h];
        __syncthreads();
        const float* w; const float* b; float* out; bool dotanh;
        if (mode == 0){ w = wW1;      b = bW1; out = g_hidW;  dotanh = true;  }
        else if (mode == 1){ w = wR1; b = bR1; out = g_hidR;  dotanh = true;  }
        else { w = wT1 + 6*HID;       b = bT1; out = g_baseT; dotanh = false; }
        float acc = b[h];
        #pragma unroll
        for (int g = 0; g < NG; g++) acc += xs[g]*w[g*HID + h];
        out[s*HID + h] = dotanh ? tanhf(acc) : acc;
    }
}

// ---------------- fcT layer-1: block per (s, t-chunk), regs-resident weights -
__global__ void __launch_bounds__(128) hiddenT_kernel(const float* __restrict__ x,
                                                      const float* __restrict__ wT1){
    const int s = blockIdx.x;
    const int t0 = blockIdx.y*TCHUNK;
    const int t1 = min(t0 + TCHUNK, NT);
    const int nt = t1 - t0;
    const int hl = threadIdx.x, hh = hl*2;

    float w0[6], w1[6];
    #pragma unroll
    for (int i = 0; i < 6; i++){
        w0[i] = wT1[i*HID + hh];
        w1[i] = wT1[i*HID + hh + 1];
    }
    const float b0 = g_baseT[s*HID + hh];
    const float b1 = g_baseT[s*HID + hh + 1];

    __shared__ float sx[TCHUNK*6];
    for (int u = hl; u < nt*6; u += 128){
        int j = u/6, i = u - j*6;
        sx[u] = x[(size_t)(t0 + j)*(NS*6) + s*6 + i];
    }
    __syncthreads();

    __half* dst = g_hiddenH + ((size_t)(t0*NS + s))*HID + hh;
    #pragma unroll 4
    for (int j = 0; j < nt; j++){
        const float* xv = sx + j*6;
        float a0 = b0, a1 = b1;
        #pragma unroll
        for (int i = 0; i < 6; i++){
            float f = xv[i];
            a0 += f*w0[i];
            a1 += f*w1[i];
        }
        *(half2*)(dst + (size_t)j*(NS*HID)) = __floats2half2_rn(tanha(a0), tanha(a1));
    }
}

// ---------------- combined small SIMT GEMMs (fcW + fcR layer 2) -------------
#define BM 128
#define BN 64
#define BK 32
#define KK 256

__global__ void __launch_bounds__(256) gemmWR_kernel(
        const float* __restrict__ Wb, const float* __restrict__ Wbias,
        const float* __restrict__ Rb, const float* __restrict__ Rbias){
    const float* A; float* C; const float* B; const float* bias; int N; int bn;
    if (blockIdx.x < 28){ A = g_hidW; C = g_w;     B = Wb; bias = Wbias; N = NH*7;  bn = blockIdx.x; }
    else                { A = g_hidR; C = g_rfraw; B = Rb; bias = Rbias; N = NH*NR; bn = blockIdx.x - 28; }

    __shared__ float As[2][BK][BM];
    __shared__ float Bs[2][BK][BN];

    const int tid = threadIdx.x;
    const int tx  = tid & 15;
    const int ty  = tid >> 4;
    const int bm  = blockIdx.y;

    const float* Ag = A + bm*BM*KK;
    const float* Bg = B + bn*BN;

    float acc[8][4];
    #pragma unroll
    for (int i = 0; i < 8; i++)
        #pragma unroll
        for (int j = 0; j < 4; j++) acc[i][j] = 0.0f;

    float4 ra[4], rb[2];
    auto ldg_tile = [&](int k0){
        #pragma unroll
        for (int i = 0; i < 4; i++){
            int f = tid + i*256;
            int row = f >> 3, c4 = f & 7;
            ra[i] = *(const float4*)(Ag + row*KK + k0 + c4*4);
        }
        #pragma unroll
        for (int i = 0; i < 2; i++){
            int f = tid + i*256;
            int row = f >> 4, c4 = f & 15;
            rb[i] = *(const float4*)(Bg + (k0 + row)*N + c4*4);
        }
    };
    auto sts_tile = [&](int buf){
        #pragma unroll
        for (int i = 0; i < 4; i++){
            int f = tid + i*256;
            int row = f >> 3, c4 = f & 7;
            As[buf][c4*4+0][row] = ra[i].x;
            As[buf][c4*4+1][row] = ra[i].y;
            As[buf][c4*4+2][row] = ra[i].z;
            As[buf][c4*4+3][row] = ra[i].w;
        }
        #pragma unroll
        for (int i = 0; i < 2; i++){
            int f = tid + i*256;
            int row = f >> 4, c4 = f & 15;
            *(float4*)&Bs[buf][row][c4*4] = rb[i];
        }
    };

    ldg_tile(0);
    sts_tile(0);
    __syncthreads();

    const int KT = KK/BK;
    int buf = 0;
    for (int kt = 0; kt < KT; kt++){
        if (kt + 1 < KT) ldg_tile((kt+1)*BK);
        #pragma unroll
        for (int k = 0; k < BK; k++){
            float4 a0 = *(const float4*)&As[buf][k][ty*8];
            float4 a1 = *(const float4*)&As[buf][k][ty*8+4];
            float4 b0 = *(const float4*)&Bs[buf][k][tx*4];
            float a[8] = {a0.x,a0.y,a0.z,a0.w,a1.x,a1.y,a1.z,a1.w};
            float b[4] = {b0.x,b0.y,b0.z,b0.w};
            #pragma unroll
            for (int i = 0; i < 8; i++)
                #pragma unroll
                for (int j = 0; j < 4; j++)
                    acc[i][j] += a[i]*b[j];
        }
        if (kt + 1 < KT){
            sts_tile(buf^1);
            __syncthreads();
            buf ^= 1;
        }
    }

    #pragma unroll
    for (int i = 0; i < 8; i++){
        int gr = bm*BM + ty*8 + i;
        #pragma unroll
        for (int j = 0; j < 4; j++){
            int gc = bn*BN + tx*4 + j;
            C[gr*N + gc] = acc[i][j] + bias[gc];
        }
    }
}

// ====== fp16 mma.sync GEMM, A-stationary, packed fp16 flux epilogue =========
#define OFF_BB 65536
#define OFF_SBIAS (OFF_BB + 4*8192)     // 98304
#define SMEM_MMA (OFF_SBIAS + 3072)     // 101376

__global__ void __launch_bounds__(256,2) gemmMMA_kernel(const float* __restrict__ x){
    extern __shared__ char smem[];
    const uint32_t sb = smem_u32(smem);
    float* sbias = (float*)(smem + OFF_SBIAS);

    const int tid  = threadIdx.x;
    const int lane = tid & 31;
    const int wid  = tid >> 5;
    const int wm   = wid >> 2;
    const int wn   = wid & 3;
    const int bm   = blockIdx.x;        // 0..729

    #pragma unroll
    for (int i = 0; i < 3; i++) sbias[tid + i*256] = g_biasP[tid + i*256];

    const __half* Asrc = g_hiddenH + (size_t)bm*128*HID;

    // ---- load full A tile: 8 chunks x 8KB ----
    {
        #pragma unroll
        for (int c = 0; c < 8; c++){
            #pragma unroll
            for (int i = 0; i < 2; i++){
                int task = tid + i*256;
                int row = task >> 2, q = task & 3;
                uint32_t col = (uint32_t)(q*16) ^ (uint32_t)(((row>>1)&3)<<4);
                cpa16(sb + c*8192 + row*64 + col, Asrc + (size_t)row*HID + c*32 + q*8);
            }
        }
    }
    auto loadB = [&](int g){
        int bnn = g >> 3, kt = g & 7, st = g & 3;
        const __half* Bsrc = g_w2tH + (size_t)bnn*128*HID;
        #pragma unroll
        for (int i = 0; i < 2; i++){
            int task = tid + i*256;
            int row = task >> 2, q = task & 3;
            uint32_t col = (uint32_t)(q*16) ^ (uint32_t)(((row>>1)&3)<<4);
            cpa16(sb + OFF_BB + st*8192 + row*64 + col, Bsrc + (size_t)row*HID + kt*32 + q*8);
        }
    };
    loadB(0); CP_COMMIT();
    loadB(1); CP_COMMIT();
    loadB(2); CP_COMMIT();

    const int arow = lane & 15;
    const uint32_t acb = (lane & 16) ? 16u : 0u;
    const uint32_t aswz = (uint32_t)(((arow>>1)&3)<<4);
    const int brow = (lane & 7) | ((lane & 16) >> 1);
    const uint32_t bcb = (lane & 8) ? 16u : 0u;
    const uint32_t bswz = (uint32_t)(((brow>>1)&3)<<4);
    uint32_t aoff[4], boff[2];
    #pragma unroll
    for (int mi = 0; mi < 4; mi++) aoff[mi] = (uint32_t)((wm*64 + mi*16 + arow)*64);
    #pragma unroll
    for (int p = 0; p < 2; p++)   boff[p]  = (uint32_t)((wn*32 + p*16 + brow)*64);

    const int qr = lane >> 2, ql = lane & 3;

    float acc[4][4][4];
    #pragma unroll
    for (int i = 0; i < 4; i++)
        #pragma unroll
        for (int j = 0; j < 4; j++)
            #pragma unroll
            for (int k = 0; k < 4; k++) acc[i][j][k] = 0.0f;

    #pragma unroll 1
    for (int g = 0; g < 48; g++){
        if (g >= 1 && g + 2 < 48){ loadB(g+2); CP_COMMIT(); }
        if (g + 2 < 48) cpwait<2>(); else if (g + 1 < 48) cpwait<1>(); else cpwait<0>();
        __syncthreads();

        const int kt = g & 7, st = g & 3;
        uint32_t abase = sb + kt*8192;
        uint32_t bbase = sb + OFF_BB + st*8192;
        #pragma unroll
        for (int ks = 0; ks < 2; ks++){
            uint32_t acol = (acb + (uint32_t)(ks*32)) ^ aswz;
            uint32_t bcol = (bcb + (uint32_t)(ks*32)) ^ bswz;
            uint32_t aF[4][4];
            uint32_t bF[4][2];
            LDSM_X4(aF[0][0],aF[0][1],aF[0][2],aF[0][3], abase + aoff[0] + acol);
            LDSM_X4(aF[1][0],aF[1][1],aF[1][2],aF[1][3], abase + aoff[1] + acol);
            LDSM_X4(aF[2][0],aF[2][1],aF[2][2],aF[2][3], abase + aoff[2] + acol);
            LDSM_X4(aF[3][0],aF[3][1],aF[3][2],aF[3][3], abase + aoff[3] + acol);
            LDSM_X4(bF[0][0],bF[0][1],bF[1][0],bF[1][1], bbase + boff[0] + bcol);
            LDSM_X4(bF[2][0],bF[2][1],bF[3][0],bF[3][1], bbase + boff[1] + bcol);
            #pragma unroll
            for (int mi = 0; mi < 4; mi++)
                #pragma unroll
                for (int ni = 0; ni < 4; ni++)
                    MMA_F16(acc[mi][ni][0],acc[mi][ni][1],acc[mi][ni][2],acc[mi][ni][3],
                            aF[mi][0],aF[mi][1],aF[mi][2],aF[mi][3],
                            bF[ni][0],bF[ni][1]);
        }

        if (kt == 7){
            const int bnn = g >> 3;
            if (bnn < 4){
                // PlEv interleaved tile: comp0 = Pl(hardsig*pf), comp1 = Ev(relu*2*Ee)
                const int hb = bnn*64 + wn*16 + ql*4;     // + ni
                #pragma unroll
                for (int mi = 0; mi < 4; mi++){
                    int r0 = bm*128 + wm*64 + mi*16 + qr;
                    int r1 = r0 + 8;
                    float pf0 = g_pfrac[r0], pf1 = g_pfrac[r1];
                    float E0 = x[r0*6 + 1], E1 = x[r1*6 + 1];
                    uint32_t u0[4], u1[4];
                    #pragma unroll
                    for (int ni = 0; ni < 4; ni++){
                        int cl = wn*32 + ni*8 + ql*2;
                        float b0v = sbias[bnn*128 + cl], b1v = sbias[bnn*128 + cl + 1];
                        float v0 = acc[mi][ni][0] + b0v;   // Pl @ r0
                        float v1 = acc[mi][ni][1] + b1v;   // Ev @ r0
                        float v2 = acc[mi][ni][2] + b0v;   // Pl @ r1
                        float v3 = acc[mi][ni][3] + b1v;   // Ev @ r1
                        float pl0 = pf0*fminf(fmaxf(v0*(2.0f/6.0f)+0.5f,0.0f),1.0f);
                        float ev0 = E0*fmaxf(v1,0.0f)*2.0f;
                        float pl1 = pf1*fminf(fmaxf(v2*(2.0f/6.0f)+0.5f,0.0f),1.0f);
                        float ev1 = E1*fmaxf(v3,0.0f)*2.0f;
                        half2 h0 = __floats2half2_rn(pl0, ev0);
                        half2 h1 = __floats2half2_rn(pl1, ev1);
                        u0[ni] = *(uint32_t*)&h0;
                        u1[ni] = *(uint32_t*)&h1;
                        acc[mi][ni][0]=0.0f; acc[mi][ni][1]=0.0f;
                        acc[mi][ni][2]=0.0f; acc[mi][ni][3]=0.0f;
                    }
                    *(uint4*)(g_PlEvH + (size_t)r0*NH + hb) = make_uint4(u0[0],u0[1],u0[2],u0[3]);
                    *(uint4*)(g_PlEvH + (size_t)r1*NH + hb) = make_uint4(u1[0],u1[1],u1[2],u1[3]);
                }
            } else {
                // Vm tile: both comps exp, packed 8 consecutive h per lane
                const int hb = (bnn-4)*128 + wn*32 + ql*8;  // + ni*2 + comp
                #pragma unroll
                for (int mi = 0; mi < 4; mi++){
                    int r0 = bm*128 + wm*64 + mi*16 + qr;
                    int r1 = r0 + 8;
                    uint32_t u0[4], u1[4];
                    #pragma unroll
                    for (int ni = 0; ni < 4; ni++){
                        int cl = wn*32 + ni*8 + ql*2;
                        float b0v = sbias[bnn*128 + cl], b1v = sbias[bnn*128 + cl + 1];
                        half2 h0 = __floats2half2_rn(expf(acc[mi][ni][0] + b0v),
                                                     expf(acc[mi][ni][1] + b1v));
                        half2 h1 = __floats2half2_rn(expf(acc[mi][ni][2] + b0v),
                                                     expf(acc[mi][ni][3] + b1v));
                        u0[ni] = *(uint32_t*)&h0;
                        u1[ni] = *(uint32_t*)&h1;
                        acc[mi][ni][0]=0.0f; acc[mi][ni][1]=0.0f;
                        acc[mi][ni][2]=0.0f; acc[mi][ni][3]=0.0f;
                    }
                    *(uint4*)((__half*)g_VmH + (size_t)r0*NH + hb) = make_uint4(u0[0],u0[1],u0[2],u0[3]);
                    *(uint4*)((__half*)g_VmH + (size_t)r1*NH + hb) = make_uint4(u1[0],u1[1],u1[2],u1[3]);
                }
            }
        }
    }
}

// ---------------- fcW + fcR activations, one launch --------------------------
__global__ void __launch_bounds__(256) actWR_kernel(){
    int h = threadIdx.x;
    if (blockIdx.x < NS){
        int s = blockIdx.x;
        const float* w = g_w + s*(NH*7);
        float kp = sigf(w[h]);
        float ks = sigf(w[NH+h]);
        float kg = sigf(w[2*NH+h])/10.0f;
        float gp = sigf(w[3*NH+h]);
        float e  = expf(w[4*NH+h]);
        float gL = e*e;
        float qb = fmaxf(w[5*NH+h], 0.0f);
        float gar = w[6*NH+h];

        __shared__ float red[8];
        float m = gar;
        #pragma unroll
        for (int o = 16; o; o >>= 1) m = fmaxf(m, __shfl_xor_sync(0xffffffffu, m, o));
        if ((h & 31) == 0) red[h>>5] = m;
        __syncthreads();
        if (h < 32){
            float v = (h < 8) ? red[h] : -1e30f;
            #pragma unroll
            for (int o = 4; o; o >>= 1) v = fmaxf(v, __shfl_xor_sync(0xffffffffu, v, o));
            if (h == 0) red[0] = v;
        }
        __syncthreads();
        float M = red[0];
        __syncthreads();
        float eg = expf(gar - M);
        float sm = eg;
        #pragma unroll
        for (int o = 16; o; o >>= 1) sm += __shfl_xor_sync(0xffffffffu, sm, o);
        if ((h & 31) == 0) red[h>>5] = sm;
        __syncthreads();
        if (h < 32){
            float v = (h < 8) ? red[h] : 0.0f;
            #pragma unroll
            for (int o = 4; o; o >>= 1) v += __shfl_xor_sync(0xffffffffu, v, o);
            if (h == 0) red[0] = v;
        }
        __syncthreads();
        float S = red[0];

        int ix = s*NH + h;
        g_kp[ix] = kp; g_ks[ix] = ks; g_kg[ix] = kg; g_gp[ix] = gp;
        g_gL[ix] = gL; g_qb[ix] = qb; g_ga[ix] = eg/S;
    } else {
        int s = blockIdx.x - NS;
        const float* rf = g_rfraw + s*(NH*NR) + h*NR;
        float v[NR];
        float m = -1e30f;
        #pragma unroll
        for (int j = 0; j < NR; j++){ v[j] = fmaxf(rf[j], 0.0f); m = fmaxf(m, v[j]); }
        float ssum = 0.0f;
        #pragma unroll
        for (int j = 0; j < NR; j++){ v[j] = expf(v[j]-m); ssum += v[j]; }
        float* out = g_r + s*(NH*NR) + h*NR;
        #pragma unroll
        for (int j = 0; j < NR; j++) out[j] = v[j]/ssum;
    }
}

// ==== fused scan + conv: packed fp16 fluxes, register ring, warp partials ===
__global__ void __launch_bounds__(256) scanconv_kernel(float* __restrict__ out){
    __shared__ float sPs[368];
    __shared__ float yW[8][368];

    const int s = blockIdx.x, tid = threadIdx.x, h = tid;
    const int w = tid >> 5;

    for (int i = tid; i < NT; i += 256) sPs[i] = g_PsT[s*QSTR + i];

    const int idx0 = (s << 8) + h;
    const float kp = g_kp[idx0], ks = g_ks[idx0], kg = g_kg[idx0];
    const float gp = g_gp[idx0], gL = g_gL[idx0], qb = g_qb[idx0];
    const float gah = g_ga[idx0];
    float c[NR];
    {
        const float* rp = g_r + (size_t)idx0*NR;
        #pragma unroll
        for (int j = 0; j < NR; j++) c[j] = gah*rp[j];
    }
    __syncthreads();

    float Sf = 0.0f, Ss = 0.0f, Sg = 0.0f;
    const size_t str = (size_t)NS*NH;
    float fl[8], fev[8], fm[8];
    {
        size_t ix = idx0;
        #pragma unroll
        for (int i = 0; i < 8; i++){
            uint32_t pe = g_PlEvH[ix];
            float2 f2 = __half22float2(*(half2*)&pe);
            fl[i] = f2.x; fev[i] = f2.y;
            fm[i] = __half2float(g_VmH[ix]);
            ix += str;
        }
    }
    size_t ixn = (size_t)idx0 + 8*str;

    float q16[16];

    auto step = [&](int tt, float cfl, float cfev, float cfm){
        float fs = sPs[tt];
        float a  = Sf + fs;
        float qf = fminf(a, cfm);
        Sf = fmaxf(a - cfm, 0.0f);
        float H  = fmaxf(Ss + cfl + qf - cfev, 0.0f);
        float qp = fmaxf(kp*(H - gL), 0.0f);
        float qsa = ks*fminf(H, gL);
        Ss = H - qp - qsa;
        float sgin = Sg + qsa*gp;
        float qg = kg*sgin + qb;
        Sg = (1.0f - kg)*sgin - qb;
        return qp + qsa*(1.0f - gp) + qg;
    };

    #pragma unroll 1
    for (int tb = 0; tb < 352; tb += 16){
        #pragma unroll
        for (int i = 0; i < 16; i++){
            int t = tb + i;
            float cfl = fl[i&7], cfev = fev[i&7], cfm = fm[i&7];
            if (t + 8 < NT){
                uint32_t pe = g_PlEvH[ixn];
                float2 f2 = __half22float2(*(half2*)&pe);
                fl[i&7] = f2.x; fev[i&7] = f2.y;
                fm[i&7] = __half2float(g_VmH[ixn]);
                ixn += str;
            }
            q16[i] = step(t, cfl, cfev, cfm);
            if (t >= 15){
                float val = 0.0f;
                #pragma unroll
                for (int j = 0; j < 16; j++) val += c[j]*q16[(i+1+j)&15];
                #pragma unroll
                for (int o = 16; o; o >>= 1) val += __shfl_xor_sync(0xffffffffu, val, o);
                if ((tid & 31) == 0) yW[w][t-15] = val;
            }
        }
    }
    #pragma unroll
    for (int i = 0; i < 13; i++){
        int t = 352 + i;
        float cfl = fl[i&7], cfev = fev[i&7], cfm = fm[i&7];
        if (t + 8 < NT){
            uint32_t pe = g_PlEvH[ixn];
            float2 f2 = __half22float2(*(half2*)&pe);
            fl[i&7] = f2.x; fev[i&7] = f2.y;
            fm[i&7] = __half2float(g_VmH[ixn]);
            ixn += str;
        }
        q16[i] = step(t, cfl, cfev, cfm);
        float val = 0.0f;
        #pragma unroll
        for (int j = 0; j < 16; j++) val += c[j]*q16[(i+1+j)&15];
        #pragma unroll
        for (int o = 16; o; o >>= 1) val += __shfl_xor_sync(0xffffffffu, val, o);
        if ((tid & 31) == 0) yW[w][t-15] = val;
    }
    __syncthreads();

    for (int t = tid; t < TOUT; t += 256){
        float acc = 0.0f;
        #pragma unroll
        for (int w2 = 0; w2 < 8; w2++) acc += yW[w2][t];
        out[t*NS + s] = acc;
    }
}

// ---------------- launch ----------------------------------------------------
extern "C" void kernel_launch(void* const* d_in, const int* in_sizes, int n_in,
                              void* d_out, int out_size){
    const float* x      = (const float*)d_in[0];
    const float* xc     = (const float*)d_in[1];
    const float* fcW_w1 = (const float*)d_in[2];
    const float* fcW_b1 = (const float*)d_in[3];
    const float* fcW_w2 = (const float*)d_in[4];
    const float* fcW_b2 = (const float*)d_in[5];
    const float* fcT_w1 = (const float*)d_in[6];
    const float* fcT_b1 = (const float*)d_in[7];
    const float* fcT_w2 = (const float*)d_in[8];
    const float* fcT_b2 = (const float*)d_in[9];
    const float* fcR_w1 = (const float*)d_in[10];
    const float* fcR_b1 = (const float*)d_in[11];
    const float* fcR_w2 = (const float*)d_in[12];
    const float* fcR_b2 = (const float*)d_in[13];
    float* out = (float*)d_out;

    cudaFuncSetAttribute(gemmMMA_kernel, cudaFuncAttributeMaxDynamicSharedMemorySize, SMEM_MMA);

    setup_kernel<<<365+192+768, 256>>>(x, xc, fcT_w2, fcT_b2,
                                       fcW_w1, fcW_b1, fcR_w1, fcR_b1, fcT_w1, fcT_b1);
    gemmWR_kernel<<<dim3(92, 2), 256>>>(fcW_w2, fcW_b2, fcR_w2, fcR_b2);
    hiddenT_kernel<<<dim3(NS, 4), 128>>>(x, fcT_w1);
    gemmMMA_kernel<<<MTILES, 256, SMEM_MMA>>>(x);
    actWR_kernel<<<2*NS, 256>>>();
    scanconv_kernel<<<NS, 256>>>(out);
}

// round 11
// speedup vs baseline: 1.9249x; 1.0918x over previous
#include <cuda_runtime.h>
#include <cuda_fp16.h>
#include <cstdint>
#include <math.h>

#define NT  365
#define NS  256
#define NH  256
#define NG  32
#define NR  16
#define HID 256
#define NTS (NT*NS)          // 93440
#define TOUT (NT-NR+1)       // 350
#define MTILES 730           // 93440/128
#define QSTR 372             // padded time stride for PsT
#define TCHUNK 92            // hiddenT t-chunk (4*92=368 >= 365)

// ---------------- scratch (device globals) ----------------------------------
__device__ __half g_hiddenH[NTS*HID];   // fcT layer-1 output (tanh, fp16)
__device__ uint32_t g_PlEvH[NTS*NH];    // packed half2 {Pl, Ev} per (t,s,h)
__device__ __half g_VmH[NTS*NH];        // Vm fp16
__device__ float g_hidW[NS*HID];
__device__ float g_hidR[NS*HID];
__device__ float g_baseT[NS*HID];
__device__ float g_w[NS*NH*7];
__device__ float g_rfraw[NS*NH*NR];
__device__ float g_PsT[NS*QSTR];        // snowfall, transposed [s][t]
__device__ float g_pfrac[NTS];
__device__ __half g_w2tH[768*HID];      // fcT_w2^T, fp16, COLUMN-PERMUTED
__device__ float g_biasP[768];          // fcT_b2, same permutation

__device__ __forceinline__ float sigf(float x){ return 1.0f/(1.0f+expf(-x)); }
__device__ __forceinline__ float tanha(float x){
    float y; asm("tanh.approx.f32 %0, %1;" : "=f"(y) : "f"(x)); return y;
}

// column permutation for the big GEMM's B matrix (see epilogue packing)
__device__ __forceinline__ int perm_srccol(int colp){
    int tile = colp >> 7, c = colp & 127;
    int wn = c >> 5, ni = (c >> 3) & 3, q = (c >> 1) & 3, comp = c & 1;
    if (tile < 4){
        int h = tile*64 + wn*16 + q*4 + ni;
        return comp*256 + h;            // comp0 -> Pl(seg0), comp1 -> Ev(seg1)
    } else {
        int h = (tile-4)*128 + wn*32 + q*8 + ni*2 + comp;
        return 512 + h;                 // Vm(seg2)
    }
}

__device__ __forceinline__ uint32_t smem_u32(const void* p){
    uint32_t a;
    asm("{ .reg .u64 t; cvta.to.shared.u64 t, %1; cvt.u32.u64 %0, t; }" : "=r"(a) : "l"(p));
    return a;
}
__device__ __forceinline__ void cpa16(uint32_t dst, const void* src){
    asm volatile("cp.async.cg.shared.global [%0], [%1], 16;" :: "r"(dst), "l"(src) : "memory");
}
#define CP_COMMIT() asm volatile("cp.async.commit_group;" ::: "memory")
template<int N> __device__ __forceinline__ void cpwait(){
    asm volatile("cp.async.wait_group %0;" :: "n"(N) : "memory");
}
#define LDSM_X4(r0,r1,r2,r3,addr) \
    asm volatile("ldmatrix.sync.aligned.m8n8.x4.shared.b16 {%0,%1,%2,%3}, [%4];" \
        : "=r"(r0),"=r"(r1),"=r"(r2),"=r"(r3) : "r"(addr))
#define MMA_F16(c0,c1,c2,c3,a0,a1,a2,a3,b0,b1) \
    asm volatile("mma.sync.aligned.m16n8k16.row.col.f32.f16.f16.f32 " \
        "{%0,%1,%2,%3}, {%4,%5,%6,%7}, {%8,%9}, {%0,%1,%2,%3};" \
        : "+f"(c0),"+f"(c1),"+f"(c2),"+f"(c3) \
        : "r"(a0),"r"(a1),"r"(a2),"r"(a3), "r"(b0),"r"(b1))

// ============ setup: prep + permuted transposeB(fp16) + layer1 ==============
__global__ void __launch_bounds__(256) setup_kernel(
        const float* __restrict__ x, const float* __restrict__ xc,
        const float* __restrict__ w2, const float* __restrict__ b2,
        const float* __restrict__ wW1, const float* __restrict__ bW1,
        const float* __restrict__ wR1, const float* __restrict__ bR1,
        const float* __restrict__ wT1, const float* __restrict__ bT1){
    __shared__ float sh[32*33];
    int bid = blockIdx.x, tid = threadIdx.x;
    if (bid < 365){
        int i = bid*256 + tid;
        float P  = x[i*6+0];
        float T1 = x[i*6+2];
        float T2 = x[i*6+3];
        float ratio = (T1+T2)/(T2-T1);
        ratio = fminf(fmaxf(ratio,-1.0f),1.0f);
        float vf = acosf(ratio)/3.1415f;
        if (T1 >= 0.0f) vf = 0.0f;
        if (T2 <= 0.0f) vf = 1.0f;
        int s = i & 255, t = i >> 8;
        g_PsT[s*QSTR + t] = P*vf;
        g_pfrac[i] = P*(1.0f-vf);
    } else if (bid < 365+192){
        int tb = bid - 365;
        int nb = (tb % 24)*32, kb = (tb / 24)*32;
        int tx = tid & 31, ty = tid >> 5;
        int src = perm_srccol(nb + tx);
        #pragma unroll
        for (int r = 0; r < 32; r += 8)
            sh[(ty+r)*33 + tx] = w2[(kb+ty+r)*768 + src];
        __syncthreads();
        #pragma unroll
        for (int r = 0; r < 32; r += 8)
            g_w2tH[(nb+ty+r)*HID + kb + tx] = __float2half(sh[tx*33 + ty + r]);
        if (kb == 0 && ty == 0) g_biasP[nb + tx] = b2[src];
    } else {
        int lb = bid - 557;
        int s = lb & 255, mode = lb >> 8, h = tid;
        float* xs = sh;
        if (h < NG) xs[h] = xc[s*NG + h];
        __syncthreads();
        const float* w; const float* b; float* out; bool dotanh;
        if (mode == 0){ w = wW1;      b = bW1; out = g_hidW;  dotanh = true;  }
        else if (mode == 1){ w = wR1; b = bR1; out = g_hidR;  dotanh = true;  }
        else { w = wT1 + 6*HID;       b = bT1; out = g_baseT; dotanh = false; }
        float acc = b[h];
        #pragma unroll
        for (int g = 0; g < NG; g++) acc += xs[g]*w[g*HID + h];
        out[s*HID + h] = dotanh ? tanhf(acc) : acc;
    }
}

// ---------------- fcT layer-1: block per (s, t-chunk), regs-resident weights -
__global__ void __launch_bounds__(128) hiddenT_kernel(const float* __restrict__ x,
                                                      const float* __restrict__ wT1){
    const int s = blockIdx.x;
    const int t0 = blockIdx.y*TCHUNK;
    const int t1 = min(t0 + TCHUNK, NT);
    const int nt = t1 - t0;
    const int hl = threadIdx.x, hh = hl*2;

    float w0[6], w1[6];
    #pragma unroll
    for (int i = 0; i < 6; i++){
        w0[i] = wT1[i*HID + hh];
        w1[i] = wT1[i*HID + hh + 1];
    }
    const float b0 = g_baseT[s*HID + hh];
    const float b1 = g_baseT[s*HID + hh + 1];

    __shared__ float sx[TCHUNK*6];
    for (int u = hl; u < nt*6; u += 128){
        int j = u/6, i = u - j*6;
        sx[u] = x[(size_t)(t0 + j)*(NS*6) + s*6 + i];
    }
    __syncthreads();

    __half* dst = g_hiddenH + ((size_t)(t0*NS + s))*HID + hh;
    #pragma unroll 4
    for (int j = 0; j < nt; j++){
        const float* xv = sx + j*6;
        float a0 = b0, a1 = b1;
        #pragma unroll
        for (int i = 0; i < 6; i++){
            float f = xv[i];
            a0 += f*w0[i];
            a1 += f*w1[i];
        }
        *(half2*)(dst + (size_t)j*(NS*HID)) = __floats2half2_rn(tanha(a0), tanha(a1));
    }
}

// ===== merged big kernel: blocks <730 run fp16 MMA GEMM; rest run fcW/fcR ===
#define BM 128
#define BN 64
#define BK 32
#define KK 256
#define OFF_BB 65536
#define OFF_SBIAS (OFF_BB + 4*8192)     // 98304
#define SMEM_MMA (OFF_SBIAS + 3072)     // 101376
#define WRBLOCKS 184

__device__ void gemmWR_path(char* smem, int bx,
        const float* __restrict__ Wb, const float* __restrict__ Wbias,
        const float* __restrict__ Rb, const float* __restrict__ Rbias){
    const float* A; float* C; const float* B; const float* bias; int N; int bn;
    int bnx = bx % 92, bm = bx / 92;
    if (bnx < 28){ A = g_hidW; C = g_w;     B = Wb; bias = Wbias; N = NH*7;  bn = bnx; }
    else         { A = g_hidR; C = g_rfraw; B = Rb; bias = Rbias; N = NH*NR; bn = bnx - 28; }

    float (*As)[BK][BM] = (float(*)[BK][BM])smem;
    float (*Bs)[BK][BN] = (float(*)[BK][BN])(smem + 2*BK*BM*4);

    const int tid = threadIdx.x;
    const int tx  = tid & 15;
    const int ty  = tid >> 4;

    const float* Ag = A + bm*BM*KK;
    const float* Bg = B + bn*BN;

    float acc[8][4];
    #pragma unroll
    for (int i = 0; i < 8; i++)
        #pragma unroll
        for (int j = 0; j < 4; j++) acc[i][j] = 0.0f;

    float4 ra[4], rb[2];
    auto ldg_tile = [&](int k0){
        #pragma unroll
        for (int i = 0; i < 4; i++){
            int f = tid + i*256;
            int row = f >> 3, c4 = f & 7;
            ra[i] = *(const float4*)(Ag + row*KK + k0 + c4*4);
        }
        #pragma unroll
        for (int i = 0; i < 2; i++){
            int f = tid + i*256;
            int row = f >> 4, c4 = f & 15;
            rb[i] = *(const float4*)(Bg + (k0 + row)*N + c4*4);
        }
    };
    auto sts_tile = [&](int buf){
        #pragma unroll
        for (int i = 0; i < 4; i++){
            int f = tid + i*256;
            int row = f >> 3, c4 = f & 7;
            As[buf][c4*4+0][row] = ra[i].x;
            As[buf][c4*4+1][row] = ra[i].y;
            As[buf][c4*4+2][row] = ra[i].z;
            As[buf][c4*4+3][row] = ra[i].w;
        }
        #pragma unroll
        for (int i = 0; i < 2; i++){
            int f = tid + i*256;
            int row = f >> 4, c4 = f & 15;
            *(float4*)&Bs[buf][row][c4*4] = rb[i];
        }
    };

    ldg_tile(0);
    sts_tile(0);
    __syncthreads();

    const int KT = KK/BK;
    int buf = 0;
    for (int kt = 0; kt < KT; kt++){
        if (kt + 1 < KT) ldg_tile((kt+1)*BK);
        #pragma unroll
        for (int k = 0; k < BK; k++){
            float4 a0 = *(const float4*)&As[buf][k][ty*8];
            float4 a1 = *(const float4*)&As[buf][k][ty*8+4];
            float4 b0 = *(const float4*)&Bs[buf][k][tx*4];
            float a[8] = {a0.x,a0.y,a0.z,a0.w,a1.x,a1.y,a1.z,a1.w};
            float b[4] = {b0.x,b0.y,b0.z,b0.w};
            #pragma unroll
            for (int i = 0; i < 8; i++)
                #pragma unroll
                for (int j = 0; j < 4; j++)
                    acc[i][j] += a[i]*b[j];
        }
        if (kt + 1 < KT){
            sts_tile(buf^1);
            __syncthreads();
            buf ^= 1;
        }
    }

    #pragma unroll
    for (int i = 0; i < 8; i++){
        int gr = bm*BM + ty*8 + i;
        #pragma unroll
        for (int j = 0; j < 4; j++){
            int gc = bn*BN + tx*4 + j;
            C[gr*N + gc] = acc[i][j] + bias[gc];
        }
    }
}

__global__ void __launch_bounds__(256,2) gemmBig_kernel(
        const float* __restrict__ x,
        const float* __restrict__ Wb, const float* __restrict__ Wbias,
        const float* __restrict__ Rb, const float* __restrict__ Rbias){
    extern __shared__ char smem[];
    if (blockIdx.x >= MTILES){
        gemmWR_path(smem, blockIdx.x - MTILES, Wb, Wbias, Rb, Rbias);
        return;
    }
    const uint32_t sb = smem_u32(smem);
    float* sbias = (float*)(smem + OFF_SBIAS);

    const int tid  = threadIdx.x;
    const int lane = tid & 31;
    const int wid  = tid >> 5;
    const int wm   = wid >> 2;
    const int wn   = wid & 3;
    const int bm   = blockIdx.x;        // 0..729

    #pragma unroll
    for (int i = 0; i < 3; i++) sbias[tid + i*256] = g_biasP[tid + i*256];

    const __half* Asrc = g_hiddenH + (size_t)bm*128*HID;

    // ---- load full A tile: 8 chunks x 8KB ----
    {
        #pragma unroll
        for (int c = 0; c < 8; c++){
            #pragma unroll
            for (int i = 0; i < 2; i++){
                int task = tid + i*256;
                int row = task >> 2, q = task & 3;
                uint32_t col = (uint32_t)(q*16) ^ (uint32_t)(((row>>1)&3)<<4);
                cpa16(sb + c*8192 + row*64 + col, Asrc + (size_t)row*HID + c*32 + q*8);
            }
        }
    }
    auto loadB = [&](int g){
        int bnn = g >> 3, kt = g & 7, st = g & 3;
        const __half* Bsrc = g_w2tH + (size_t)bnn*128*HID;
        #pragma unroll
        for (int i = 0; i < 2; i++){
            int task = tid + i*256;
            int row = task >> 2, q = task & 3;
            uint32_t col = (uint32_t)(q*16) ^ (uint32_t)(((row>>1)&3)<<4);
            cpa16(sb + OFF_BB + st*8192 + row*64 + col, Bsrc + (size_t)row*HID + kt*32 + q*8);
        }
    };
    loadB(0); CP_COMMIT();
    loadB(1); CP_COMMIT();
    loadB(2); CP_COMMIT();

    const int arow = lane & 15;
    const uint32_t acb = (lane & 16) ? 16u : 0u;
    const uint32_t aswz = (uint32_t)(((arow>>1)&3)<<4);
    const int brow = (lane & 7) | ((lane & 16) >> 1);
    const uint32_t bcb = (lane & 8) ? 16u : 0u;
    const uint32_t bswz = (uint32_t)(((brow>>1)&3)<<4);
    uint32_t aoff[4], boff[2];
    #pragma unroll
    for (int mi = 0; mi < 4; mi++) aoff[mi] = (uint32_t)((wm*64 + mi*16 + arow)*64);
    #pragma unroll
    for (int p = 0; p < 2; p++)   boff[p]  = (uint32_t)((wn*32 + p*16 + brow)*64);

    const int qr = lane >> 2, ql = lane & 3;

    float acc[4][4][4];
    #pragma unroll
    for (int i = 0; i < 4; i++)
        #pragma unroll
        for (int j = 0; j < 4; j++)
            #pragma unroll
            for (int k = 0; k < 4; k++) acc[i][j][k] = 0.0f;

    #pragma unroll 1
    for (int g = 0; g < 48; g++){
        if (g >= 1 && g + 2 < 48){ loadB(g+2); CP_COMMIT(); }
        if (g + 2 < 48) cpwait<2>(); else if (g + 1 < 48) cpwait<1>(); else cpwait<0>();
        __syncthreads();

        const int kt = g & 7, st = g & 3;
        uint32_t abase = sb + kt*8192;
        uint32_t bbase = sb + OFF_BB + st*8192;
        #pragma unroll
        for (int ks = 0; ks < 2; ks++){
            uint32_t acol = (acb + (uint32_t)(ks*32)) ^ aswz;
            uint32_t bcol = (bcb + (uint32_t)(ks*32)) ^ bswz;
            uint32_t aF[4][4];
            uint32_t bF[4][2];
            LDSM_X4(aF[0][0],aF[0][1],aF[0][2],aF[0][3], abase + aoff[0] + acol);
            LDSM_X4(aF[1][0],aF[1][1],aF[1][2],aF[1][3], abase + aoff[1] + acol);
            LDSM_X4(aF[2][0],aF[2][1],aF[2][2],aF[2][3], abase + aoff[2] + acol);
            LDSM_X4(aF[3][0],aF[3][1],aF[3][2],aF[3][3], abase + aoff[3] + acol);
            LDSM_X4(bF[0][0],bF[0][1],bF[1][0],bF[1][1], bbase + boff[0] + bcol);
            LDSM_X4(bF[2][0],bF[2][1],bF[3][0],bF[3][1], bbase + boff[1] + bcol);
            #pragma unroll
            for (int mi = 0; mi < 4; mi++)
                #pragma unroll
                for (int ni = 0; ni < 4; ni++)
                    MMA_F16(acc[mi][ni][0],acc[mi][ni][1],acc[mi][ni][2],acc[mi][ni][3],
                            aF[mi][0],aF[mi][1],aF[mi][2],aF[mi][3],
                            bF[ni][0],bF[ni][1]);
        }

        if (kt == 7){
            const int bnn = g >> 3;
            if (bnn < 4){
                const int hb = bnn*64 + wn*16 + ql*4;     // + ni
                #pragma unroll
                for (int mi = 0; mi < 4; mi++){
                    int r0 = bm*128 + wm*64 + mi*16 + qr;
                    int r1 = r0 + 8;
                    float pf0 = g_pfrac[r0], pf1 = g_pfrac[r1];
                    float E0 = x[r0*6 + 1], E1 = x[r1*6 + 1];
                    uint32_t u0[4], u1[4];
                    #pragma unroll
                    for (int ni = 0; ni < 4; ni++){
                        int cl = wn*32 + ni*8 + ql*2;
                        float b0v = sbias[bnn*128 + cl], b1v = sbias[bnn*128 + cl + 1];
                        float v0 = acc[mi][ni][0] + b0v;
                        float v1 = acc[mi][ni][1] + b1v;
                        float v2 = acc[mi][ni][2] + b0v;
                        float v3 = acc[mi][ni][3] + b1v;
                        float pl0 = pf0*fminf(fmaxf(v0*(2.0f/6.0f)+0.5f,0.0f),1.0f);
                        float ev0 = E0*fmaxf(v1,0.0f)*2.0f;
                        float pl1 = pf1*fminf(fmaxf(v2*(2.0f/6.0f)+0.5f,0.0f),1.0f);
                        float ev1 = E1*fmaxf(v3,0.0f)*2.0f;
                        half2 h0 = __floats2half2_rn(pl0, ev0);
                        half2 h1 = __floats2half2_rn(pl1, ev1);
                        u0[ni] = *(uint32_t*)&h0;
                        u1[ni] = *(uint32_t*)&h1;
                        acc[mi][ni][0]=0.0f; acc[mi][ni][1]=0.0f;
                        acc[mi][ni][2]=0.0f; acc[mi][ni][3]=0.0f;
                    }
                    *(uint4*)(g_PlEvH + (size_t)r0*NH + hb) = make_uint4(u0[0],u0[1],u0[2],u0[3]);
                    *(uint4*)(g_PlEvH + (size_t)r1*NH + hb) = make_uint4(u1[0],u1[1],u1[2],u1[3]);
                }
            } else {
                const int hb = (bnn-4)*128 + wn*32 + ql*8;
                #pragma unroll
                for (int mi = 0; mi < 4; mi++){
                    int r0 = bm*128 + wm*64 + mi*16 + qr;
                    int r1 = r0 + 8;
                    uint32_t u0[4], u1[4];
                    #pragma unroll
                    for (int ni = 0; ni < 4; ni++){
                        int cl = wn*32 + ni*8 + ql*2;
                        float b0v = sbias[bnn*128 + cl], b1v = sbias[bnn*128 + cl + 1];
                        half2 h0 = __floats2half2_rn(expf(acc[mi][ni][0] + b0v),
                                                     expf(acc[mi][ni][1] + b1v));
                        half2 h1 = __floats2half2_rn(expf(acc[mi][ni][2] + b0v),
                                                     expf(acc[mi][ni][3] + b1v));
                        u0[ni] = *(uint32_t*)&h0;
                        u1[ni] = *(uint32_t*)&h1;
                        acc[mi][ni][0]=0.0f; acc[mi][ni][1]=0.0f;
                        acc[mi][ni][2]=0.0f; acc[mi][ni][3]=0.0f;
                    }
                    *(uint4*)((__half*)g_VmH + (size_t)r0*NH + hb) = make_uint4(u0[0],u0[1],u0[2],u0[3]);
                    *(uint4*)((__half*)g_VmH + (size_t)r1*NH + hb) = make_uint4(u1[0],u1[1],u1[2],u1[3]);
                }
            }
        }
    }
}

// ==== fused actWR + scan + conv ==============================================
__global__ void __launch_bounds__(256) scanconv_kernel(float* __restrict__ out){
    __shared__ float sPs[368];
    __shared__ float yW[8][368];
    __shared__ float red[8];

    const int s = blockIdx.x, tid = threadIdx.x, h = tid;
    const int w = tid >> 5;

    for (int i = tid; i < NT; i += 256) sPs[i] = g_PsT[s*QSTR + i];

    const int idx0 = (s << 8) + h;

    // ---- fcW activations (was actWR) ----
    const float* wrow = g_w + s*(NH*7);
    const float kp = sigf(wrow[h]);
    const float ks = sigf(wrow[NH+h]);
    const float kg = sigf(wrow[2*NH+h])/10.0f;
    const float gp = sigf(wrow[3*NH+h]);
    float e税 = expf(wrow[4*NH+h]);
    const float gL = e税*e税;
    const float qb = fmaxf(wrow[5*NH+h], 0.0f);
    float gar = wrow[6*NH+h];

    // block softmax over h for ga
    float m = gar;
    #pragma unroll
    for (int o = 16; o; o >>= 1) m = fmaxf(m, __shfl_xor_sync(0xffffffffu, m, o));
    if ((h & 31) == 0) red[h>>5] = m;
    __syncthreads();
    if (h < 32){
        float v = (h < 8) ? red[h] : -1e30f;
        #pragma unroll
        for (int o = 4; o; o >>= 1) v = fmaxf(v, __shfl_xor_sync(0xffffffffu, v, o));
        if (h == 0) red[0] = v;
    }
    __syncthreads();
    float M = red[0];
    __syncthreads();
    float eg = expf(gar - M);
    float sm = eg;
    #pragma unroll
    for (int o = 16; o; o >>= 1) sm += __shfl_xor_sync(0xffffffffu, sm, o);
    if ((h & 31) == 0) red[h>>5] = sm;
    __syncthreads();
    if (h < 32){
        float v = (h < 8) ? red[h] : 0.0f;
        #pragma unroll
        for (int o = 4; o; o >>= 1) v += __shfl_xor_sync(0xffffffffu, v, o);
        if (h == 0) red[0] = v;
    }
    __syncthreads();
    const float gah = eg/red[0];

    // ---- fcR relu+softmax (was actWR) -> conv taps pre-scaled by ga ----
    float c[NR];
    {
        const float* rf = g_rfraw + (size_t)idx0*NR;
        float v[NR];
        float mm = -1e30f;
        #pragma unroll
        for (int j = 0; j < NR; j++){ v[j] = fmaxf(rf[j], 0.0f); mm = fmaxf(mm, v[j]); }
        float ssum = 0.0f;
        #pragma unroll
        for (int j = 0; j < NR; j++){ v[j] = expf(v[j]-mm); ssum += v[j]; }
        float inv = gah/ssum;
        #pragma unroll
        for (int j = 0; j < NR; j++) c[j] = v[j]*inv;
    }

    float Sf = 0.0f, Ss = 0.0f, Sg = 0.0f;
    const size_t str = (size_t)NS*NH;
    float fl[8], fev[8], fm[8];
    {
        size_t ix = idx0;
        #pragma unroll
        for (int i = 0; i < 8; i++){
            uint32_t pe = g_PlEvH[ix];
            float2 f2 = __half22float2(*(half2*)&pe);
            fl[i] = f2.x; fev[i] = f2.y;
            fm[i] = __half2float(g_VmH[ix]);
            ix += str;
        }
    }
    size_t ixn = (size_t)idx0 + 8*str;

    float q16[16];

    auto step = [&](int tt, float cfl, float cfev, float cfm){
        float fs = sPs[tt];
        float a  = Sf + fs;
        float qf = fminf(a, cfm);
        Sf = fmaxf(a - cfm, 0.0f);
        float H  = fmaxf(Ss + cfl + qf - cfev, 0.0f);
        float qp = fmaxf(kp*(H - gL), 0.0f);
        float qsa = ks*fminf(H, gL);
        Ss = H - qp - qsa;
        float sgin = Sg + qsa*gp;
        float qg = kg*sgin + qb;
        Sg = (1.0f - kg)*sgin - qb;
        return qp + qsa*(1.0f - gp) + qg;
    };

    #pragma unroll 1
    for (int tb = 0; tb < 352; tb += 16){
        #pragma unroll
        for (int i = 0; i < 16; i++){
            int t = tb + i;
            float cfl = fl[i&7], cfev = fev[i&7], cfm = fm[i&7];
            if (t + 8 < NT){
                uint32_t pe = g_PlEvH[ixn];
                float2 f2 = __half22float2(*(half2*)&pe);
                fl[i&7] = f2.x; fev[i&7] = f2.y;
                fm[i&7] = __half2float(g_VmH[ixn]);
                ixn += str;
            }
            q16[i] = step(t, cfl, cfev, cfm);
            if (t >= 15){
                float val = 0.0f;
                #pragma unroll
                for (int j = 0; j < 16; j++) val += c[j]*q16[(i+1+j)&15];
                #pragma unroll
                for (int o = 16; o; o >>= 1) val += __shfl_xor_sync(0xffffffffu, val, o);
                if ((tid & 31) == 0) yW[w][t-15] = val;
            }
        }
    }
    #pragma unroll
    for (int i = 0; i < 13; i++){
        int t = 352 + i;
        float cfl = fl[i&7], cfev = fev[i&7], cfm = fm[i&7];
        if (t + 8 < NT){
            uint32_t pe = g_PlEvH[ixn];
            float2 f2 = __half22float2(*(half2*)&pe);
            fl[i&7] = f2.x; fev[i&7] = f2.y;
            fm[i&7] = __half2float(g_VmH[ixn]);
            ixn += str;
        }
        q16[i] = step(t, cfl, cfev, cfm);
        float val = 0.0f;
        #pragma unroll
        for (int j = 0; j < 16; j++) val += c[j]*q16[(i+1+j)&15];
        #pragma unroll
        for (int o = 16; o; o >>= 1) val += __shfl_xor_sync(0xffffffffu, val, o);
        if ((tid & 31) == 0) yW[w][t-15] = val;
    }
    __syncthreads();

    for (int t = tid; t < TOUT; t += 256){
        float acc = 0.0f;
        #pragma unroll
        for (int w2 = 0; w2 < 8; w2++) acc += yW[w2][t];
        out[t*NS + s] = acc;
    }
}

// ---------------- launch ----------------------------------------------------
extern "C" void kernel_launch(void* const* d_in, const int* in_sizes, int n_in,
                              void* d_out, int out_size){
    const float* x      = (const float*)d_in[0];
    const float* xc     = (const float*)d_in[1];
    const float* fcW_w1 = (const float*)d_in[2];
    const float* fcW_b1 = (const float*)d_in[3];
    const float* fcW_w2 = (const float*)d_in[4];
    const float* fcW_b2 = (const float*)d_in[5];
    const float* fcT_w1 = (const float*)d_in[6];
    const float* fcT_b1 = (const float*)d_in[7];
    const float* fcT_w2 = (const float*)d_in[8];
    const float* fcT_b2 = (const float*)d_in[9];
    const float* fcR_w1 = (const float*)d_in[10];
    const float* fcR_b1 = (const float*)d_in[11];
    const float* fcR_w2 = (const float*)d_in[12];
    const float* fcR_b2 = (const float*)d_in[13];
    float* out = (float*)d_out;

    cudaFuncSetAttribute(gemmBig_kernel, cudaFuncAttributeMaxDynamicSharedMemorySize, SMEM_MMA);

    setup_kernel<<<365+192+768, 256>>>(x, xc, fcT_w2, fcT_b2,
                                       fcW_w1, fcW_b1, fcR_w1, fcR_b1, fcT_w1, fcT_b1);
    hiddenT_kernel<<<dim3(NS, 4), 128>>>(x, fcT_w1);
    gemmBig_kernel<<<MTILES + WRBLOCKS, 256, SMEM_MMA>>>(x, fcW_w2, fcW_b2, fcR_w2, fcR_b2);
    scanconv_kernel<<<NS, 256>>>(out);
}